// round 12
// baseline (speedup 1.0000x reference)
#include <cuda_runtime.h>
#include <cuda_fp16.h>
#include <cstdint>

#define LATENT 16
#define HID 512
#define DD 64
#define NB 128
#define NG 128
#define OUTSZ 12610
#define OUTSZ_PAD 12612

// Scratch (device globals — no allocation allowed)
__device__ float g_h0[NB * HID];
__device__ __half g_h1h[NB * HID];     // fp16-hi split of h1, [m][k]
__device__ __half g_h1l[NB * HID];     // fp16-lo split of h1, [m][k]
__device__ float g_wb[NB * OUTSZ_PAD]; // PRE-PERMUTED into decoder layout

typedef unsigned long long u64;

__device__ __forceinline__ u64 pack2(float lo, float hi) {
    u64 r; asm("mov.b64 %0, {%1, %2};" : "=l"(r) : "f"(lo), "f"(hi)); return r;
}
__device__ __forceinline__ void fma2(u64& d, u64 a, u64 b) {
    asm("fma.rn.f32x2 %0, %1, %2, %0;" : "+l"(d) : "l"(a), "l"(b));
}

__device__ __forceinline__ float leaky(float x) { return x > 0.0f ? x : 0.01f * x; }

// fast sin: 2-step Cody-Waite range reduction + MUFU sin (args stay < ~40)
__device__ __forceinline__ float fsin(float x) {
    float k = rintf(x * 0.15915494309189535f);
    x = fmaf(k, -6.28125f, x);
    x = fmaf(k, -1.9353071795864769e-3f, x);
    return __sinf(x);
}

// pack two fp32 into one u32 of 2 fp16 (lo half = first arg)
__device__ __forceinline__ uint32_t packh2(float vlo, float vhi) {
    uint32_t d;
    asm("cvt.rn.f16x2.f32 %0, %1, %2;" : "=r"(d) : "f"(vhi), "f"(vlo));
    return d;
}

// fp16 mma m16n8k16 (fragment mappings validated rounds 10-11)
__device__ __forceinline__ void mma_f16(float4& c, const uint32_t a[4],
                                        const uint32_t b[2]) {
    asm volatile(
        "mma.sync.aligned.m16n8k16.row.col.f32.f16.f16.f32 "
        "{%0,%1,%2,%3}, {%4,%5,%6,%7}, {%8,%9}, {%0,%1,%2,%3};"
        : "+f"(c.x), "+f"(c.y), "+f"(c.z), "+f"(c.w)
        : "r"(a[0]), "r"(a[1]), "r"(a[2]), "r"(a[3]), "r"(b[0]), "r"(b[1]));
}

// Decoder layout (floats): W1[0,4096) W2[4096,8192) W3[8192,12288) W0[12288,12352)
// b1[12352,12416) b2[12416,12480) b3[12480,12544) W4[12544,12608) b0[12608] b4[12609]
#define OFF_W0 12288
#define OFF_B  12352
#define OFF_W4 12544

__device__ __forceinline__ int perm_wb(int n) {
    if (n < 4161)  return (n < 64) ? 12288 + n : (n == 64 ? 12608 : n - 65);
    if (n < 8321)  return (n < 4225) ? 12352 + (n - 4161) : 4096 + (n - 4225);
    if (n < 12481) return (n < 8385) ? 12416 + (n - 8321) : 8192 + (n - 8385);
    if (n < 12545) return 12480 + (n - 12481);
    return (n < 12609) ? 12544 + (n - 12545) : 12609;
}

// ---------------------------------------------------------------------------
// Kernel 1: h0 = leaky_relu(z @ hw0 + hb0)
// ---------------------------------------------------------------------------
__global__ void k_h0(const float* __restrict__ z, const float* __restrict__ hw0,
                     const float* __restrict__ hb0) {
    int b = blockIdx.x;
    int j = threadIdx.x;
    const float* zr = z + b * LATENT;
    float acc = hb0[j];
#pragma unroll
    for (int k = 0; k < LATENT; k++) acc = fmaf(zr[k], hw0[k * HID + j], acc);
    g_h0[b * HID + j] = leaky(acc);
}

// ---------------------------------------------------------------------------
// FFMA GEMM for h1, prefetch pipeline; fp16 hi/lo split output [m][k].
// ---------------------------------------------------------------------------
#define H1_BM 16
#define H1_BN 64
#define H1_BK 16

__global__ void __launch_bounds__(128)
gemm_h1(const float* __restrict__ A, const float* __restrict__ B,
        const float* __restrict__ bias,
        __half* __restrict__ Ch, __half* __restrict__ Cl) {
    constexpr int N = HID, K = HID;
    __shared__ __align__(16) u64 As[H1_BK][H1_BM];
    __shared__ __align__(16) float Bs[H1_BK][H1_BN];

    int tid = threadIdx.x;
    int tx = tid & 15, ty = tid >> 4;
    int m0 = blockIdx.y * H1_BM, n0 = blockIdx.x * H1_BN;

    u64 acc[2][2];
#pragma unroll
    for (int i = 0; i < 2; i++)
#pragma unroll
        for (int j = 0; j < 2; j++) acc[i][j] = pack2(0.0f, 0.0f);

    float4 pa;
    float pb[8];
    int par = tid >> 2, pac4 = tid & 3;
    int pbn = tid & 63, pbk0 = tid >> 6;

    auto ldg_tile = [&](int k0, float4& a4, float pbv[8]) {
        if (tid < 64)
            a4 = *(const float4*)&A[(size_t)(m0 + par) * K + k0 + pac4 * 4];
#pragma unroll
        for (int r = 0; r < 8; r++)
            pbv[r] = B[(size_t)(k0 + pbk0 + r * 2) * N + n0 + pbn];
    };
    auto sts_tile = [&](const float4& a4, const float pbv[8]) {
        if (tid < 64) {
            As[pac4 * 4 + 0][par] = pack2(a4.x, a4.x);
            As[pac4 * 4 + 1][par] = pack2(a4.y, a4.y);
            As[pac4 * 4 + 2][par] = pack2(a4.z, a4.z);
            As[pac4 * 4 + 3][par] = pack2(a4.w, a4.w);
        }
#pragma unroll
        for (int r = 0; r < 8; r++) Bs[pbk0 + r * 2][pbn] = pbv[r];
    };

    ldg_tile(0, pa, pb);
    sts_tile(pa, pb);
    __syncthreads();

    for (int t = 0; t < K / H1_BK; t++) {
        if (t + 1 < K / H1_BK) ldg_tile((t + 1) * H1_BK, pa, pb);
#pragma unroll
        for (int k = 0; k < H1_BK; k++) {
            u64 ra0 = As[k][ty * 2], ra1 = As[k][ty * 2 + 1];
            u64 rb0 = *(const u64*)&Bs[k][tx * 2];
            u64 rb1 = *(const u64*)&Bs[k][tx * 2 + 32];
            fma2(acc[0][0], ra0, rb0); fma2(acc[0][1], ra0, rb1);
            fma2(acc[1][0], ra1, rb0); fma2(acc[1][1], ra1, rb1);
        }
        __syncthreads();
        if (t + 1 < K / H1_BK) {
            sts_tile(pa, pb);
            __syncthreads();
        }
    }

#pragma unroll
    for (int i = 0; i < 2; i++) {
        int m = m0 + ty * 2 + i;
#pragma unroll
        for (int j = 0; j < 2; j++) {
            float lo, hi;
            asm("mov.b64 {%0, %1}, %2;" : "=f"(lo), "=f"(hi) : "l"(acc[i][j]));
            int n = n0 + tx * 2 + j * 32;
            float v0 = leaky(lo + bias[n]);
            float v1 = leaky(hi + bias[n + 1]);
            float h0f = __half2float(__float2half_rn(v0));
            float h1f = __half2float(__float2half_rn(v1));
            *(uint32_t*)&Ch[(size_t)m * HID + n] = packh2(h0f, h1f);
            *(uint32_t*)&Cl[(size_t)m * HID + n] = packh2(v0 - h0f, v1 - h1f);
        }
    }
}

// ---------------------------------------------------------------------------
// wb GEMM via fp16 mma (2-split): 132 CTAs x 512 threads (16 warps),
// CTA tile M=128 x N=96, K-step 32; warp tile m32 x n24 (wm=wid&3, wn=wid>>2).
// A smem [m][72 halves] (frag banks 4g4+t4, conflict-free); B smem [n][74].
// ---------------------------------------------------------------------------
#define KT 32
#define BNW 96
#define ASTR 72
#define BSTR 74
#define WB_SMEM_BYTES ((2 * 128 * ASTR + 2 * BNW * BSTR) * 2)

__global__ void __launch_bounds__(512)
k_wbgemm(const __half* __restrict__ Ah_g, const __half* __restrict__ Al_g,
         const float* __restrict__ Bg, const float* __restrict__ bias,
         float* __restrict__ Cout) {
    extern __shared__ __align__(16) __half smh[];
    __half* As_h = smh;
    __half* As_l = smh + 128 * ASTR;
    __half* Bs_h = smh + 2 * 128 * ASTR;
    __half* Bs_l = Bs_h + BNW * BSTR;

    int tid = threadIdx.x;
    int lane = tid & 31;
    int wid = tid >> 5;
    int g4 = lane >> 2;
    int t4 = lane & 3;
    int wm = wid & 3;        // m-quarter (32 rows)
    int wn = wid >> 2;       // n-quarter (24 cols)
    int n0 = blockIdx.x * BNW;

    float4 acc[2][3];
#pragma unroll
    for (int i = 0; i < 2; i++)
#pragma unroll
        for (int j = 0; j < 3; j++) acc[i][j] = make_float4(0.f, 0.f, 0.f, 0.f);

    u64 pah[2], pal[2];
    float pb[6];

    auto ldg_tile = [&](int kt) {
#pragma unroll
        for (int i = 0; i < 2; i++) {
            int idx = tid + i * 512;          // 1024 u64 slots (128 rows x 8)
            int m = idx >> 3, j = idx & 7;
            pah[i] = *(const u64*)&Ah_g[(size_t)m * HID + kt + j * 4];
            pal[i] = *(const u64*)&Al_g[(size_t)m * HID + kt + j * 4];
        }
#pragma unroll
        for (int r = 0; r < 6; r++) {
            int idx = tid + r * 512;          // 3072 = 32k x 96n
            int n = idx % BNW, k = idx / BNW;
            int gn = n0 + n;
            pb[r] = (gn < OUTSZ) ? Bg[(size_t)(kt + k) * OUTSZ + gn] : 0.0f;
        }
    };
    auto sts_tile = [&]() {
#pragma unroll
        for (int i = 0; i < 2; i++) {
            int idx = tid + i * 512;
            int m = idx >> 3, j = idx & 7;
            *(u64*)&As_h[m * ASTR + j * 4] = pah[i];
            *(u64*)&As_l[m * ASTR + j * 4] = pal[i];
        }
#pragma unroll
        for (int r = 0; r < 6; r++) {
            int idx = tid + r * 512;
            int n = idx % BNW, k = idx / BNW;
            float hf = __half2float(__float2half_rn(pb[r]));
            Bs_h[n * BSTR + k] = __float2half_rn(hf);
            Bs_l[n * BSTR + k] = __float2half_rn(pb[r] - hf);
        }
    };

    ldg_tile(0);
    sts_tile();
    __syncthreads();

    for (int t = 0; t < HID / KT; t++) {
        if (t + 1 < HID / KT) ldg_tile((t + 1) * KT);

#pragma unroll
        for (int ks = 0; ks < KT; ks += 16) {
            uint32_t ah[2][4], al[2][4];
#pragma unroll
            for (int mf = 0; mf < 2; mf++) {
                int m = wm * 32 + mf * 16 + g4;
                ah[mf][0] = *(const uint32_t*)&As_h[m * ASTR + ks + 2 * t4];
                ah[mf][1] = *(const uint32_t*)&As_h[(m + 8) * ASTR + ks + 2 * t4];
                ah[mf][2] = *(const uint32_t*)&As_h[m * ASTR + ks + 2 * t4 + 8];
                ah[mf][3] = *(const uint32_t*)&As_h[(m + 8) * ASTR + ks + 2 * t4 + 8];
                al[mf][0] = *(const uint32_t*)&As_l[m * ASTR + ks + 2 * t4];
                al[mf][1] = *(const uint32_t*)&As_l[(m + 8) * ASTR + ks + 2 * t4];
                al[mf][2] = *(const uint32_t*)&As_l[m * ASTR + ks + 2 * t4 + 8];
                al[mf][3] = *(const uint32_t*)&As_l[(m + 8) * ASTR + ks + 2 * t4 + 8];
            }
#pragma unroll
            for (int nf = 0; nf < 3; nf++) {
                int n = wn * 24 + nf * 8 + g4;
                uint32_t bh[2], bl[2];
                bh[0] = *(const uint32_t*)&Bs_h[n * BSTR + ks + 2 * t4];
                bh[1] = *(const uint32_t*)&Bs_h[n * BSTR + ks + 2 * t4 + 8];
                bl[0] = *(const uint32_t*)&Bs_l[n * BSTR + ks + 2 * t4];
                bl[1] = *(const uint32_t*)&Bs_l[n * BSTR + ks + 2 * t4 + 8];
#pragma unroll
                for (int mf = 0; mf < 2; mf++) {
                    mma_f16(acc[mf][nf], ah[mf], bh);
                    mma_f16(acc[mf][nf], ah[mf], bl);
                    mma_f16(acc[mf][nf], al[mf], bh);
                }
            }
        }
        __syncthreads();
        if (t + 1 < HID / KT) {
            sts_tile();
            __syncthreads();
        }
    }

    // epilogue: bias + permuted scatter
#pragma unroll
    for (int mf = 0; mf < 2; mf++) {
        int m = wm * 32 + mf * 16 + g4;
#pragma unroll
        for (int nf = 0; nf < 3; nf++) {
            int n = n0 + wn * 24 + nf * 8 + t4 * 2;
            if (n < OUTSZ) {
                Cout[(size_t)m * OUTSZ_PAD + perm_wb(n)] = acc[mf][nf].x + bias[n];
                Cout[(size_t)(m + 8) * OUTSZ_PAD + perm_wb(n)] = acc[mf][nf].z + bias[n];
            }
            if (n + 1 < OUTSZ) {
                Cout[(size_t)m * OUTSZ_PAD + perm_wb(n + 1)] = acc[mf][nf].y + bias[n + 1];
                Cout[(size_t)(m + 8) * OUTSZ_PAD + perm_wb(n + 1)] = acc[mf][nf].w + bias[n + 1];
            }
        }
    }
}

// ---------------------------------------------------------------------------
// Decoder via fp16 mma (2-split), 512 threads (16 warps: wm 0..7 m16,
// wn 0..1 n32). X fp16 [m][72 halves]; W transposed fp16 [n][72 halves].
// Fragment loads conflict-free (banks 4g4+t4 both).
// ---------------------------------------------------------------------------
#define XSH 72
#define WSH 72
#define XBUFH (NG * XSH)          // 9216 halves
#define WBUFH (DD * WSH)          // 4608 halves
#define DEC_SMEM_BYTES ((4 * XBUFH + 2 * WBUFH) * 2 + 512 * 4)

__global__ void __launch_bounds__(512)
k_decode(const float* __restrict__ logP, float* __restrict__ out) {
    extern __shared__ __align__(16) __half smh[];
    __half* XAh = smh;
    __half* XAl = smh + XBUFH;
    __half* XBh = smh + 2 * XBUFH;
    __half* XBl = smh + 3 * XBUFH;
    __half* Wth = smh + 4 * XBUFH;
    __half* Wtl = smh + 4 * XBUFH + WBUFH;
    float* part = (float*)(smh + 4 * XBUFH + 2 * WBUFH);

    int b = blockIdx.x;
    int tid = threadIdx.x;
    int lane = tid & 31;
    int wid = tid >> 5;
    int g4 = lane >> 2;
    int t4 = lane & 3;
    int wm = wid & 7;          // m-sixteenth (16 rows)
    int wn = wid >> 3;         // n-half (32 cols)
    const float* brow = g_wb + (size_t)b * OUTSZ_PAD;

    // ---- first layer: X0 = sin(30*(xin*W0 + b0)), fp16 hi/lo ----
    {
        int g = tid & (NG - 1);
        int q = tid >> 7;                    // 0..3
        float xin = logP[b * NG + g];
        float b0v = brow[12608];
#pragma unroll
        for (int jj = 0; jj < 16; jj += 2) {
            int j = q * 16 + jj;
            float v0 = fsin(30.0f * fmaf(xin, brow[OFF_W0 + j], b0v));
            float v1 = fsin(30.0f * fmaf(xin, brow[OFF_W0 + j + 1], b0v));
            float h0 = __half2float(__float2half_rn(v0));
            float h1 = __half2float(__float2half_rn(v1));
            *(uint32_t*)&XAh[g * XSH + j] = packh2(h0, h1);
            *(uint32_t*)&XAl[g * XSH + j] = packh2(v0 - h0, v1 - h1);
        }
    }
    __syncthreads();

#pragma unroll 1
    for (int it = 0; it < 3; it++) {
        // W transposed staging: Wt[j][i] fp16 hi/lo (8 elements per thread)
        {
            const float* Wg = brow + it * DD * DD;
            int i = tid >> 3, j0 = (tid & 7) * 8;
            float4 wa = *(const float4*)&Wg[i * DD + j0];
            float4 wb4 = *(const float4*)&Wg[i * DD + j0 + 4];
            float wv[8] = {wa.x, wa.y, wa.z, wa.w, wb4.x, wb4.y, wb4.z, wb4.w};
#pragma unroll
            for (int jj = 0; jj < 8; jj++) {
                int j = j0 + jj;
                float hf = __half2float(__float2half_rn(wv[jj]));
                Wth[j * WSH + i] = __float2half_rn(hf);
                Wtl[j * WSH + i] = __float2half_rn(wv[jj] - hf);
            }
        }
        float biasE[4], biasO[4];
#pragma unroll
        for (int nf = 0; nf < 4; nf++) {
            int col = wn * 32 + nf * 8 + 2 * t4;
            biasE[nf] = brow[OFF_B + it * DD + col];
            biasO[nf] = brow[OFF_B + it * DD + col + 1];
        }
        __syncthreads();

        const __half* Xih = (it & 1) ? XBh : XAh;
        const __half* Xil = (it & 1) ? XBl : XAl;
        __half* Xoh = (it & 1) ? XAh : XBh;
        __half* Xol = (it & 1) ? XAl : XBl;

        float4 acc[4];
#pragma unroll
        for (int nf = 0; nf < 4; nf++)
            acc[nf] = make_float4(biasE[nf], biasO[nf], biasE[nf], biasO[nf]);

        int m = wm * 16 + g4;
#pragma unroll
        for (int k16 = 0; k16 < DD; k16 += 16) {
            uint32_t ah[4], al[4];
            ah[0] = *(const uint32_t*)&Xih[m * XSH + k16 + 2 * t4];
            ah[1] = *(const uint32_t*)&Xih[(m + 8) * XSH + k16 + 2 * t4];
            ah[2] = *(const uint32_t*)&Xih[m * XSH + k16 + 2 * t4 + 8];
            ah[3] = *(const uint32_t*)&Xih[(m + 8) * XSH + k16 + 2 * t4 + 8];
            al[0] = *(const uint32_t*)&Xil[m * XSH + k16 + 2 * t4];
            al[1] = *(const uint32_t*)&Xil[(m + 8) * XSH + k16 + 2 * t4];
            al[2] = *(const uint32_t*)&Xil[m * XSH + k16 + 2 * t4 + 8];
            al[3] = *(const uint32_t*)&Xil[(m + 8) * XSH + k16 + 2 * t4 + 8];
#pragma unroll
            for (int nf = 0; nf < 4; nf++) {
                int n = wn * 32 + nf * 8 + g4;
                uint32_t bh[2], bl[2];
                bh[0] = *(const uint32_t*)&Wth[n * WSH + k16 + 2 * t4];
                bh[1] = *(const uint32_t*)&Wth[n * WSH + k16 + 2 * t4 + 8];
                bl[0] = *(const uint32_t*)&Wtl[n * WSH + k16 + 2 * t4];
                bl[1] = *(const uint32_t*)&Wtl[n * WSH + k16 + 2 * t4 + 8];
                mma_f16(acc[nf], ah, bh);
                mma_f16(acc[nf], ah, bl);
                mma_f16(acc[nf], al, bh);
            }
        }

        // sin + split + store (c0,c1 -> row m; c2,c3 -> row m+8)
#pragma unroll
        for (int nf = 0; nf < 4; nf++) {
            int col = wn * 32 + nf * 8 + 2 * t4;
            float4 a = acc[nf];
            float v0 = fsin(a.x), v1 = fsin(a.y);
            float v2 = fsin(a.z), v3 = fsin(a.w);
            float h0 = __half2float(__float2half_rn(v0));
            float h1 = __half2float(__float2half_rn(v1));
            float h2 = __half2float(__float2half_rn(v2));
            float h3 = __half2float(__float2half_rn(v3));
            *(uint32_t*)&Xoh[m * XSH + col] = packh2(h0, h1);
            *(uint32_t*)&Xol[m * XSH + col] = packh2(v0 - h0, v1 - h1);
            *(uint32_t*)&Xoh[(m + 8) * XSH + col] = packh2(h2, h3);
            *(uint32_t*)&Xol[(m + 8) * XSH + col] = packh2(v2 - h2, v3 - h3);
        }
        __syncthreads();
    }

    // ---- final layer: out[g] = (X3 . W4) + b4 (X3 in XB after it=2) ----
    {
        int g = tid & (NG - 1);
        int q = tid >> 7;
        float s = 0.0f;
#pragma unroll
        for (int ii = 0; ii < 16; ii++) {
            int i = q * 16 + ii;
            float xv = __half2float(XBh[g * XSH + i]) + __half2float(XBl[g * XSH + i]);
            s = fmaf(xv, brow[OFF_W4 + i], s);
        }
        part[q * NG + g] = s;
    }
    __syncthreads();
    if (tid < NG) {
        float acc = brow[12609] + part[tid] + part[NG + tid]
                  + part[2 * NG + tid] + part[3 * NG + tid];
        out[b * NG + tid] = fmaf(acc, 500.0f, 1500.0f);
    }
}

// ---------------------------------------------------------------------------
extern "C" void kernel_launch(void* const* d_in, const int* in_sizes, int n_in,
                              void* d_out, int out_size) {
    (void)in_sizes; (void)n_in; (void)out_size;
    const float* z    = (const float*)d_in[0];
    const float* logP = (const float*)d_in[1];
    const float* hw0  = (const float*)d_in[2];
    const float* hb0  = (const float*)d_in[3];
    const float* hw1  = (const float*)d_in[4];
    const float* hb1  = (const float*)d_in[5];
    const float* hw2  = (const float*)d_in[6];
    const float* hb2  = (const float*)d_in[7];
    float* out = (float*)d_out;

    float *p_h0, *p_wb;
    __half *p_h1h, *p_h1l;
    cudaGetSymbolAddress((void**)&p_h0, g_h0);
    cudaGetSymbolAddress((void**)&p_h1h, g_h1h);
    cudaGetSymbolAddress((void**)&p_h1l, g_h1l);
    cudaGetSymbolAddress((void**)&p_wb, g_wb);

    cudaFuncSetAttribute(k_decode, cudaFuncAttributeMaxDynamicSharedMemorySize,
                         DEC_SMEM_BYTES);
    cudaFuncSetAttribute(k_wbgemm, cudaFuncAttributeMaxDynamicSharedMemorySize,
                         WB_SMEM_BYTES);

    // 1) h0
    k_h0<<<NB, HID>>>(z, hw0, hb0);

    // 2) h1 = leaky(h0 @ hw1 + hb1), fp16 hi/lo split output
    {
        dim3 grid(HID / H1_BN, NB / H1_BM);   // 64 blocks
        gemm_h1<<<grid, 128>>>(p_h0, hw1, hb1, p_h1h, p_h1l);
    }

    // 3) wb = h1 @ hw2 + hb2 via fp16 mma (2-split), 132 CTAs x 512 thr
    k_wbgemm<<<(OUTSZ + BNW - 1) / BNW, 512, WB_SMEM_BYTES>>>(
        p_h1h, p_h1l, hw2, hb2, p_wb);

    // 4) decoder on tensor cores (fp16 2-split)
    k_decode<<<NB, 512, DEC_SMEM_BYTES>>>(logP, out);
}

// round 13
// speedup vs baseline: 1.0530x; 1.0530x over previous
#include <cuda_runtime.h>
#include <cuda_fp16.h>
#include <cstdint>

#define LATENT 16
#define HID 512
#define DD 64
#define NB 128
#define NG 128
#define OUTSZ 12610
#define OUTSZ_PAD 12612

// Scratch (device globals — no allocation allowed)
__device__ float g_h0[NB * HID];
__device__ __half g_h1h[NB * HID];     // fp16-hi split of h1, [m][k]
__device__ __half g_h1l[NB * HID];     // fp16-lo split of h1, [m][k]
__device__ float g_wb[NB * OUTSZ_PAD]; // PRE-PERMUTED into decoder layout

typedef unsigned long long u64;

__device__ __forceinline__ u64 pack2(float lo, float hi) {
    u64 r; asm("mov.b64 %0, {%1, %2};" : "=l"(r) : "f"(lo), "f"(hi)); return r;
}
__device__ __forceinline__ void fma2(u64& d, u64 a, u64 b) {
    asm("fma.rn.f32x2 %0, %1, %2, %0;" : "+l"(d) : "l"(a), "l"(b));
}

__device__ __forceinline__ float leaky(float x) { return x > 0.0f ? x : 0.01f * x; }

// fast sin: 2-step Cody-Waite range reduction + MUFU sin (args stay < ~40)
__device__ __forceinline__ float fsin(float x) {
    float k = rintf(x * 0.15915494309189535f);
    x = fmaf(k, -6.28125f, x);
    x = fmaf(k, -1.9353071795864769e-3f, x);
    return __sinf(x);
}

// pack two fp32 into one u32 of 2 fp16 (lo half = first arg)
__device__ __forceinline__ uint32_t packh2(float vlo, float vhi) {
    uint32_t d;
    asm("cvt.rn.f16x2.f32 %0, %1, %2;" : "=r"(d) : "f"(vhi), "f"(vlo));
    return d;
}

// fp16 mma m16n8k16 (fragment mappings validated rounds 10-12)
__device__ __forceinline__ void mma_f16(float4& c, const uint32_t a[4],
                                        const uint32_t b[2]) {
    asm volatile(
        "mma.sync.aligned.m16n8k16.row.col.f32.f16.f16.f32 "
        "{%0,%1,%2,%3}, {%4,%5,%6,%7}, {%8,%9}, {%0,%1,%2,%3};"
        : "+f"(c.x), "+f"(c.y), "+f"(c.z), "+f"(c.w)
        : "r"(a[0]), "r"(a[1]), "r"(a[2]), "r"(a[3]), "r"(b[0]), "r"(b[1]));
}

// Decoder layout (floats): W1[0,4096) W2[4096,8192) W3[8192,12288) W0[12288,12352)
// b1[12352,12416) b2[12416,12480) b3[12480,12544) W4[12544,12608) b0[12608] b4[12609]
#define OFF_W0 12288
#define OFF_B  12352
#define OFF_W4 12544

__device__ __forceinline__ int perm_wb(int n) {
    if (n < 4161)  return (n < 64) ? 12288 + n : (n == 64 ? 12608 : n - 65);
    if (n < 8321)  return (n < 4225) ? 12352 + (n - 4161) : 4096 + (n - 4225);
    if (n < 12481) return (n < 8385) ? 12416 + (n - 8321) : 8192 + (n - 8385);
    if (n < 12545) return 12480 + (n - 12481);
    return (n < 12609) ? 12544 + (n - 12545) : 12609;
}

// ---------------------------------------------------------------------------
// Kernel 1: h0 = leaky_relu(z @ hw0 + hb0)
// ---------------------------------------------------------------------------
__global__ void k_h0(const float* __restrict__ z, const float* __restrict__ hw0,
                     const float* __restrict__ hb0) {
    int b = blockIdx.x;
    int j = threadIdx.x;
    const float* zr = z + b * LATENT;
    float acc = hb0[j];
#pragma unroll
    for (int k = 0; k < LATENT; k++) acc = fmaf(zr[k], hw0[k * HID + j], acc);
    g_h0[b * HID + j] = leaky(acc);
}

// ---------------------------------------------------------------------------
// FFMA GEMM for h1, DOUBLE-BUFFERED (one sync per K-tile); fp16 hi/lo split
// output [m][k].
// ---------------------------------------------------------------------------
#define H1_BM 16
#define H1_BN 64
#define H1_BK 16

__global__ void __launch_bounds__(128)
gemm_h1(const float* __restrict__ A, const float* __restrict__ B,
        const float* __restrict__ bias,
        __half* __restrict__ Ch, __half* __restrict__ Cl) {
    constexpr int N = HID, K = HID;
    __shared__ __align__(16) u64 As[2][H1_BK][H1_BM];
    __shared__ __align__(16) float Bs[2][H1_BK][H1_BN];

    int tid = threadIdx.x;
    int tx = tid & 15, ty = tid >> 4;
    int m0 = blockIdx.y * H1_BM, n0 = blockIdx.x * H1_BN;

    u64 acc[2][2];
#pragma unroll
    for (int i = 0; i < 2; i++)
#pragma unroll
        for (int j = 0; j < 2; j++) acc[i][j] = pack2(0.0f, 0.0f);

    float4 pa;
    float pb[8];
    int par = tid >> 2, pac4 = tid & 3;
    int pbn = tid & 63, pbk0 = tid >> 6;

    auto ldg_tile = [&](int k0) {
        if (tid < 64)
            pa = *(const float4*)&A[(size_t)(m0 + par) * K + k0 + pac4 * 4];
#pragma unroll
        for (int r = 0; r < 8; r++)
            pb[r] = B[(size_t)(k0 + pbk0 + r * 2) * N + n0 + pbn];
    };
    auto sts_tile = [&](int s) {
        if (tid < 64) {
            As[s][pac4 * 4 + 0][par] = pack2(pa.x, pa.x);
            As[s][pac4 * 4 + 1][par] = pack2(pa.y, pa.y);
            As[s][pac4 * 4 + 2][par] = pack2(pa.z, pa.z);
            As[s][pac4 * 4 + 3][par] = pack2(pa.w, pa.w);
        }
#pragma unroll
        for (int r = 0; r < 8; r++) Bs[s][pbk0 + r * 2][pbn] = pb[r];
    };

    ldg_tile(0);
    sts_tile(0);
    __syncthreads();

    int p = 0;
    for (int t = 0; t < K / H1_BK; t++) {
        if (t + 1 < K / H1_BK) ldg_tile((t + 1) * H1_BK);
#pragma unroll
        for (int k = 0; k < H1_BK; k++) {
            u64 ra0 = As[p][k][ty * 2], ra1 = As[p][k][ty * 2 + 1];
            u64 rb0 = *(const u64*)&Bs[p][k][tx * 2];
            u64 rb1 = *(const u64*)&Bs[p][k][tx * 2 + 32];
            fma2(acc[0][0], ra0, rb0); fma2(acc[0][1], ra0, rb1);
            fma2(acc[1][0], ra1, rb0); fma2(acc[1][1], ra1, rb1);
        }
        if (t + 1 < K / H1_BK) {
            sts_tile(p ^ 1);
            __syncthreads();
        }
        p ^= 1;
    }

#pragma unroll
    for (int i = 0; i < 2; i++) {
        int m = m0 + ty * 2 + i;
#pragma unroll
        for (int j = 0; j < 2; j++) {
            float lo, hi;
            asm("mov.b64 {%0, %1}, %2;" : "=f"(lo), "=f"(hi) : "l"(acc[i][j]));
            int n = n0 + tx * 2 + j * 32;
            float v0 = leaky(lo + bias[n]);
            float v1 = leaky(hi + bias[n + 1]);
            float h0f = __half2float(__float2half_rn(v0));
            float h1f = __half2float(__float2half_rn(v1));
            *(uint32_t*)&Ch[(size_t)m * HID + n] = packh2(h0f, h1f);
            *(uint32_t*)&Cl[(size_t)m * HID + n] = packh2(v0 - h0f, v1 - h1f);
        }
    }
}

// ---------------------------------------------------------------------------
// wb GEMM via fp16 mma (2-split), 132 CTAs x 256 threads (R11 tiling:
// warp m64 x n24), DOUBLE-BUFFERED smem (one sync per K-tile).
// A smem [m][72 halves]; B smem [n][74 halves]. 130.5 KB total.
// ---------------------------------------------------------------------------
#define KT 32
#define BNW 96
#define ASTR 72
#define BSTR 74
#define STG_H (2 * 128 * ASTR + 2 * BNW * BSTR)   // halves per stage
#define WB_SMEM_BYTES (2 * STG_H * 2)

__global__ void __launch_bounds__(256)
k_wbgemm(const __half* __restrict__ Ah_g, const __half* __restrict__ Al_g,
         const float* __restrict__ Bg, const float* __restrict__ bias,
         float* __restrict__ Cout) {
    extern __shared__ __align__(16) __half smh[];

    int tid = threadIdx.x;
    int lane = tid & 31;
    int wid = tid >> 5;
    int g4 = lane >> 2;
    int t4 = lane & 3;
    int wm = wid & 1;        // m-half (64 rows)
    int wn = wid >> 1;       // n-quarter (24 cols)
    int n0 = blockIdx.x * BNW;

    int bn = tid % BNW, bkh = tid / BNW;     // B staging: threads < 192
    bool bact = tid < 192;
    bool bok = bact && (n0 + bn) < OUTSZ;

    float4 acc[4][3];
#pragma unroll
    for (int i = 0; i < 4; i++)
#pragma unroll
        for (int j = 0; j < 3; j++) acc[i][j] = make_float4(0.f, 0.f, 0.f, 0.f);

    u64 pah[4], pal[4];
    float pb[16];

    auto ldg_tile = [&](int kt) {
#pragma unroll
        for (int i = 0; i < 4; i++) {
            int idx = tid + i * 256;          // 1024 u64 slots (128 rows x 8)
            int m = idx >> 3, j = idx & 7;
            pah[i] = *(const u64*)&Ah_g[(size_t)m * HID + kt + j * 4];
            pal[i] = *(const u64*)&Al_g[(size_t)m * HID + kt + j * 4];
        }
        if (bact) {
            const float* bp = Bg + (size_t)(kt + bkh * 16) * OUTSZ + n0 + bn;
#pragma unroll
            for (int j = 0; j < 16; j++)
                pb[j] = bok ? bp[(size_t)j * OUTSZ] : 0.0f;
        }
    };
    auto sts_tile = [&](int s) {
        __half* As_h = smh + s * STG_H;
        __half* As_l = As_h + 128 * ASTR;
        __half* Bs_h = As_l + 128 * ASTR;
        __half* Bs_l = Bs_h + BNW * BSTR;
#pragma unroll
        for (int i = 0; i < 4; i++) {
            int idx = tid + i * 256;
            int m = idx >> 3, j = idx & 7;
            *(u64*)&As_h[m * ASTR + j * 4] = pah[i];
            *(u64*)&As_l[m * ASTR + j * 4] = pal[i];
        }
        if (bact) {
#pragma unroll
            for (int j = 0; j < 8; j++) {
                float v0 = pb[2 * j], v1 = pb[2 * j + 1];
                float h0 = __half2float(__float2half_rn(v0));
                float h1 = __half2float(__float2half_rn(v1));
                *(uint32_t*)&Bs_h[bn * BSTR + bkh * 16 + 2 * j] = packh2(h0, h1);
                *(uint32_t*)&Bs_l[bn * BSTR + bkh * 16 + 2 * j] =
                    packh2(v0 - h0, v1 - h1);
            }
        }
    };

    ldg_tile(0);
    sts_tile(0);
    __syncthreads();

    int p = 0;
    for (int t = 0; t < HID / KT; t++) {
        if (t + 1 < HID / KT) ldg_tile((t + 1) * KT);

        const __half* As_h = smh + p * STG_H;
        const __half* As_l = As_h + 128 * ASTR;
        const __half* Bs_h = As_l + 128 * ASTR;
        const __half* Bs_l = Bs_h + BNW * BSTR;

#pragma unroll
        for (int ks = 0; ks < KT; ks += 16) {
            uint32_t ah[4][4], al[4][4];
#pragma unroll
            for (int mf = 0; mf < 4; mf++) {
                int m = wm * 64 + mf * 16 + g4;
                ah[mf][0] = *(const uint32_t*)&As_h[m * ASTR + ks + 2 * t4];
                ah[mf][1] = *(const uint32_t*)&As_h[(m + 8) * ASTR + ks + 2 * t4];
                ah[mf][2] = *(const uint32_t*)&As_h[m * ASTR + ks + 2 * t4 + 8];
                ah[mf][3] = *(const uint32_t*)&As_h[(m + 8) * ASTR + ks + 2 * t4 + 8];
                al[mf][0] = *(const uint32_t*)&As_l[m * ASTR + ks + 2 * t4];
                al[mf][1] = *(const uint32_t*)&As_l[(m + 8) * ASTR + ks + 2 * t4];
                al[mf][2] = *(const uint32_t*)&As_l[m * ASTR + ks + 2 * t4 + 8];
                al[mf][3] = *(const uint32_t*)&As_l[(m + 8) * ASTR + ks + 2 * t4 + 8];
            }
#pragma unroll
            for (int nf = 0; nf < 3; nf++) {
                int n = wn * 24 + nf * 8 + g4;
                uint32_t bh[2], bl[2];
                bh[0] = *(const uint32_t*)&Bs_h[n * BSTR + ks + 2 * t4];
                bh[1] = *(const uint32_t*)&Bs_h[n * BSTR + ks + 2 * t4 + 8];
                bl[0] = *(const uint32_t*)&Bs_l[n * BSTR + ks + 2 * t4];
                bl[1] = *(const uint32_t*)&Bs_l[n * BSTR + ks + 2 * t4 + 8];
#pragma unroll
                for (int mf = 0; mf < 4; mf++) {
                    mma_f16(acc[mf][nf], ah[mf], bh);
                    mma_f16(acc[mf][nf], ah[mf], bl);
                    mma_f16(acc[mf][nf], al[mf], bh);
                }
            }
        }
        if (t + 1 < HID / KT) {
            sts_tile(p ^ 1);
            __syncthreads();
        }
        p ^= 1;
    }

    // epilogue: bias + permuted scatter
#pragma unroll
    for (int mf = 0; mf < 4; mf++) {
        int m = wm * 64 + mf * 16 + g4;
#pragma unroll
        for (int nf = 0; nf < 3; nf++) {
            int n = n0 + wn * 24 + nf * 8 + t4 * 2;
            if (n < OUTSZ) {
                Cout[(size_t)m * OUTSZ_PAD + perm_wb(n)] = acc[mf][nf].x + bias[n];
                Cout[(size_t)(m + 8) * OUTSZ_PAD + perm_wb(n)] = acc[mf][nf].z + bias[n];
            }
            if (n + 1 < OUTSZ) {
                Cout[(size_t)m * OUTSZ_PAD + perm_wb(n + 1)] = acc[mf][nf].y + bias[n + 1];
                Cout[(size_t)(m + 8) * OUTSZ_PAD + perm_wb(n + 1)] = acc[mf][nf].w + bias[n + 1];
            }
        }
    }
}

// ---------------------------------------------------------------------------
// Decoder via fp16 mma (2-split), 512 threads (16 warps: wm 0..7 m16,
// wn 0..1 n32). X fp16 [m][72 halves]; W transposed fp16 [n][72 halves].
// ---------------------------------------------------------------------------
#define XSH 72
#define WSH 72
#define XBUFH (NG * XSH)          // 9216 halves
#define WBUFH (DD * WSH)          // 4608 halves
#define DEC_SMEM_BYTES ((4 * XBUFH + 2 * WBUFH) * 2 + 512 * 4)

__global__ void __launch_bounds__(512)
k_decode(const float* __restrict__ logP, float* __restrict__ out) {
    extern __shared__ __align__(16) __half smh[];
    __half* XAh = smh;
    __half* XAl = smh + XBUFH;
    __half* XBh = smh + 2 * XBUFH;
    __half* XBl = smh + 3 * XBUFH;
    __half* Wth = smh + 4 * XBUFH;
    __half* Wtl = smh + 4 * XBUFH + WBUFH;
    float* part = (float*)(smh + 4 * XBUFH + 2 * WBUFH);

    int b = blockIdx.x;
    int tid = threadIdx.x;
    int lane = tid & 31;
    int wid = tid >> 5;
    int g4 = lane >> 2;
    int t4 = lane & 3;
    int wm = wid & 7;          // m-sixteenth (16 rows)
    int wn = wid >> 3;         // n-half (32 cols)
    const float* brow = g_wb + (size_t)b * OUTSZ_PAD;

    // ---- first layer: X0 = sin(30*(xin*W0 + b0)), fp16 hi/lo ----
    {
        int g = tid & (NG - 1);
        int q = tid >> 7;                    // 0..3
        float xin = logP[b * NG + g];
        float b0v = brow[12608];
#pragma unroll
        for (int jj = 0; jj < 16; jj += 2) {
            int j = q * 16 + jj;
            float v0 = fsin(30.0f * fmaf(xin, brow[OFF_W0 + j], b0v));
            float v1 = fsin(30.0f * fmaf(xin, brow[OFF_W0 + j + 1], b0v));
            float h0 = __half2float(__float2half_rn(v0));
            float h1 = __half2float(__float2half_rn(v1));
            *(uint32_t*)&XAh[g * XSH + j] = packh2(h0, h1);
            *(uint32_t*)&XAl[g * XSH + j] = packh2(v0 - h0, v1 - h1);
        }
    }
    __syncthreads();

#pragma unroll 1
    for (int it = 0; it < 3; it++) {
        // W transposed staging: Wt[j][i] fp16 hi/lo (8 elements per thread)
        {
            const float* Wg = brow + it * DD * DD;
            int i = tid >> 3, j0 = (tid & 7) * 8;
            float4 wa = *(const float4*)&Wg[i * DD + j0];
            float4 wb4 = *(const float4*)&Wg[i * DD + j0 + 4];
            float wv[8] = {wa.x, wa.y, wa.z, wa.w, wb4.x, wb4.y, wb4.z, wb4.w};
#pragma unroll
            for (int jj = 0; jj < 8; jj++) {
                int j = j0 + jj;
                float hf = __half2float(__float2half_rn(wv[jj]));
                Wth[j * WSH + i] = __float2half_rn(hf);
                Wtl[j * WSH + i] = __float2half_rn(wv[jj] - hf);
            }
        }
        float biasE[4], biasO[4];
#pragma unroll
        for (int nf = 0; nf < 4; nf++) {
            int col = wn * 32 + nf * 8 + 2 * t4;
            biasE[nf] = brow[OFF_B + it * DD + col];
            biasO[nf] = brow[OFF_B + it * DD + col + 1];
        }
        __syncthreads();

        const __half* Xih = (it & 1) ? XBh : XAh;
        const __half* Xil = (it & 1) ? XBl : XAl;
        __half* Xoh = (it & 1) ? XAh : XBh;
        __half* Xol = (it & 1) ? XAl : XBl;

        float4 acc[4];
#pragma unroll
        for (int nf = 0; nf < 4; nf++)
            acc[nf] = make_float4(biasE[nf], biasO[nf], biasE[nf], biasO[nf]);

        int m = wm * 16 + g4;
#pragma unroll
        for (int k16 = 0; k16 < DD; k16 += 16) {
            uint32_t ah[4], al[4];
            ah[0] = *(const uint32_t*)&Xih[m * XSH + k16 + 2 * t4];
            ah[1] = *(const uint32_t*)&Xih[(m + 8) * XSH + k16 + 2 * t4];
            ah[2] = *(const uint32_t*)&Xih[m * XSH + k16 + 2 * t4 + 8];
            ah[3] = *(const uint32_t*)&Xih[(m + 8) * XSH + k16 + 2 * t4 + 8];
            al[0] = *(const uint32_t*)&Xil[m * XSH + k16 + 2 * t4];
            al[1] = *(const uint32_t*)&Xil[(m + 8) * XSH + k16 + 2 * t4];
            al[2] = *(const uint32_t*)&Xil[m * XSH + k16 + 2 * t4 + 8];
            al[3] = *(const uint32_t*)&Xil[(m + 8) * XSH + k16 + 2 * t4 + 8];
#pragma unroll
            for (int nf = 0; nf < 4; nf++) {
                int n = wn * 32 + nf * 8 + g4;
                uint32_t bh[2], bl[2];
                bh[0] = *(const uint32_t*)&Wth[n * WSH + k16 + 2 * t4];
                bh[1] = *(const uint32_t*)&Wth[n * WSH + k16 + 2 * t4 + 8];
                bl[0] = *(const uint32_t*)&Wtl[n * WSH + k16 + 2 * t4];
                bl[1] = *(const uint32_t*)&Wtl[n * WSH + k16 + 2 * t4 + 8];
                mma_f16(acc[nf], ah, bh);
                mma_f16(acc[nf], ah, bl);
                mma_f16(acc[nf], al, bh);
            }
        }

        // sin + split + store (c0,c1 -> row m; c2,c3 -> row m+8)
#pragma unroll
        for (int nf = 0; nf < 4; nf++) {
            int col = wn * 32 + nf * 8 + 2 * t4;
            float4 a = acc[nf];
            float v0 = fsin(a.x), v1 = fsin(a.y);
            float v2 = fsin(a.z), v3 = fsin(a.w);
            float h0 = __half2float(__float2half_rn(v0));
            float h1 = __half2float(__float2half_rn(v1));
            float h2 = __half2float(__float2half_rn(v2));
            float h3 = __half2float(__float2half_rn(v3));
            *(uint32_t*)&Xoh[m * XSH + col] = packh2(h0, h1);
            *(uint32_t*)&Xol[m * XSH + col] = packh2(v0 - h0, v1 - h1);
            *(uint32_t*)&Xoh[(m + 8) * XSH + col] = packh2(h2, h3);
            *(uint32_t*)&Xol[(m + 8) * XSH + col] = packh2(v2 - h2, v3 - h3);
        }
        __syncthreads();
    }

    // ---- final layer: out[g] = (X3 . W4) + b4 (X3 in XB after it=2) ----
    {
        int g = tid & (NG - 1);
        int q = tid >> 7;
        float s = 0.0f;
#pragma unroll
        for (int ii = 0; ii < 16; ii++) {
            int i = q * 16 + ii;
            float xv = __half2float(XBh[g * XSH + i]) + __half2float(XBl[g * XSH + i]);
            s = fmaf(xv, brow[OFF_W4 + i], s);
        }
        part[q * NG + g] = s;
    }
    __syncthreads();
    if (tid < NG) {
        float acc = brow[12609] + part[tid] + part[NG + tid]
                  + part[2 * NG + tid] + part[3 * NG + tid];
        out[b * NG + tid] = fmaf(acc, 500.0f, 1500.0f);
    }
}

// ---------------------------------------------------------------------------
extern "C" void kernel_launch(void* const* d_in, const int* in_sizes, int n_in,
                              void* d_out, int out_size) {
    (void)in_sizes; (void)n_in; (void)out_size;
    const float* z    = (const float*)d_in[0];
    const float* logP = (const float*)d_in[1];
    const float* hw0  = (const float*)d_in[2];
    const float* hb0  = (const float*)d_in[3];
    const float* hw1  = (const float*)d_in[4];
    const float* hb1  = (const float*)d_in[5];
    const float* hw2  = (const float*)d_in[6];
    const float* hb2  = (const float*)d_in[7];
    float* out = (float*)d_out;

    float *p_h0, *p_wb;
    __half *p_h1h, *p_h1l;
    cudaGetSymbolAddress((void**)&p_h0, g_h0);
    cudaGetSymbolAddress((void**)&p_h1h, g_h1h);
    cudaGetSymbolAddress((void**)&p_h1l, g_h1l);
    cudaGetSymbolAddress((void**)&p_wb, g_wb);

    cudaFuncSetAttribute(k_decode, cudaFuncAttributeMaxDynamicSharedMemorySize,
                         DEC_SMEM_BYTES);
    cudaFuncSetAttribute(k_wbgemm, cudaFuncAttributeMaxDynamicSharedMemorySize,
                         WB_SMEM_BYTES);

    // 1) h0
    k_h0<<<NB, HID>>>(z, hw0, hb0);

    // 2) h1 = leaky(h0 @ hw1 + hb1), fp16 hi/lo split output
    {
        dim3 grid(HID / H1_BN, NB / H1_BM);   // 64 blocks
        gemm_h1<<<grid, 128>>>(p_h0, hw1, hb1, p_h1h, p_h1l);
    }

    // 3) wb = h1 @ hw2 + hb2 via fp16 mma (2-split), 132 CTAs x 256 thr,
    //    double-buffered
    k_wbgemm<<<(OUTSZ + BNW - 1) / BNW, 256, WB_SMEM_BYTES>>>(
        p_h1h, p_h1l, hw2, hb2, p_wb);

    // 4) decoder on tensor cores (fp16 2-split)
    k_decode<<<NB, 512, DEC_SMEM_BYTES>>>(logP, out);
}

// round 14
// speedup vs baseline: 1.1502x; 1.0923x over previous
#include <cuda_runtime.h>
#include <cuda_fp16.h>
#include <cstdint>

#define LATENT 16
#define HID 512
#define DD 64
#define NB 128
#define NG 128
#define OUTSZ 12610
#define OUTSZ_PAD 12612

// Scratch (device globals — no allocation allowed)
__device__ __half g_h1h[NB * HID];     // fp16-hi split of h1, [m][k]
__device__ __half g_h1l[NB * HID];     // fp16-lo split of h1, [m][k]
__device__ float g_wb[NB * OUTSZ_PAD]; // PRE-PERMUTED into decoder layout

typedef unsigned long long u64;

__device__ __forceinline__ u64 pack2(float lo, float hi) {
    u64 r; asm("mov.b64 %0, {%1, %2};" : "=l"(r) : "f"(lo), "f"(hi)); return r;
}
__device__ __forceinline__ void fma2(u64& d, u64 a, u64 b) {
    asm("fma.rn.f32x2 %0, %1, %2, %0;" : "+l"(d) : "l"(a), "l"(b));
}

__device__ __forceinline__ float leaky(float x) { return x > 0.0f ? x : 0.01f * x; }

// fast sin: 2-step Cody-Waite range reduction + MUFU sin (args stay < ~40)
__device__ __forceinline__ float fsin(float x) {
    float k = rintf(x * 0.15915494309189535f);
    x = fmaf(k, -6.28125f, x);
    x = fmaf(k, -1.9353071795864769e-3f, x);
    return __sinf(x);
}

// pack two fp32 into one u32 of 2 fp16 (lo half = first arg)
__device__ __forceinline__ uint32_t packh2(float vlo, float vhi) {
    uint32_t d;
    asm("cvt.rn.f16x2.f32 %0, %1, %2;" : "=r"(d) : "f"(vhi), "f"(vlo));
    return d;
}

__device__ __forceinline__ uint32_t smem_u32(const void* p) {
    uint32_t a;
    asm("{ .reg .u64 t; cvta.to.shared.u64 t, %1; cvt.u32.u64 %0, t; }"
        : "=r"(a) : "l"(p));
    return a;
}

// ldmatrix: 4 / 2 8x8 b16 matrices per warp-collective instruction
__device__ __forceinline__ void ldsm4(uint32_t* r, uint32_t a) {
    asm volatile("ldmatrix.sync.aligned.m8n8.x4.shared.b16 {%0,%1,%2,%3}, [%4];"
                 : "=r"(r[0]), "=r"(r[1]), "=r"(r[2]), "=r"(r[3]) : "r"(a));
}
__device__ __forceinline__ void ldsm2(uint32_t* r, uint32_t a) {
    asm volatile("ldmatrix.sync.aligned.m8n8.x2.shared.b16 {%0,%1}, [%2];"
                 : "=r"(r[0]), "=r"(r[1]) : "r"(a));
}

// fp16 mma m16n8k16 (fragment mappings validated rounds 10-13)
__device__ __forceinline__ void mma_f16(float4& c, const uint32_t a[4],
                                        const uint32_t b[2]) {
    asm volatile(
        "mma.sync.aligned.m16n8k16.row.col.f32.f16.f16.f32 "
        "{%0,%1,%2,%3}, {%4,%5,%6,%7}, {%8,%9}, {%0,%1,%2,%3};"
        : "+f"(c.x), "+f"(c.y), "+f"(c.z), "+f"(c.w)
        : "r"(a[0]), "r"(a[1]), "r"(a[2]), "r"(a[3]), "r"(b[0]), "r"(b[1]));
}

// Decoder layout (floats): W1[0,4096) W2[4096,8192) W3[8192,12288) W0[12288,12352)
// b1[12352,12416) b2[12416,12480) b3[12480,12544) W4[12544,12608) b0[12608] b4[12609]
#define OFF_W0 12288
#define OFF_B  12352
#define OFF_W4 12544

__device__ __forceinline__ int perm_wb(int n) {
    if (n < 4161)  return (n < 64) ? 12288 + n : (n == 64 ? 12608 : n - 65);
    if (n < 8321)  return (n < 4225) ? 12352 + (n - 4161) : 4096 + (n - 4225);
    if (n < 12481) return (n < 8385) ? 12416 + (n - 8321) : 8192 + (n - 8385);
    if (n < 12545) return 12480 + (n - 12481);
    return (n < 12609) ? 12544 + (n - 12545) : 12609;
}

// ---------------------------------------------------------------------------
// h1 GEMM with FUSED h0: each CTA computes its 16-row h0 tile (K=16, cheap)
// into duplicated-u64 smem, then runs the double-buffered FFMA GEMM over it.
// Output: fp16 hi/lo split of h1 in [m][k] layout.
// ---------------------------------------------------------------------------
#define H1_BM 16
#define H1_BN 64
#define H1_BK 16
#define H1_AD_STR 17
#define H1_SMEM_BYTES (HID * H1_AD_STR * 8 + 2 * H1_BK * H1_BN * 4 + 16 * 16 * 4)

__global__ void __launch_bounds__(128)
gemm_h1(const float* __restrict__ z, const float* __restrict__ hw0,
        const float* __restrict__ hb0,
        const float* __restrict__ B, const float* __restrict__ bias,
        __half* __restrict__ Ch, __half* __restrict__ Cl) {
    extern __shared__ __align__(16) unsigned char smraw[];
    u64* Ad = (u64*)smraw;                                 // [512][17] dup h0
    float* Bsf = (float*)(smraw + HID * H1_AD_STR * 8);    // [2][16][64]
    float* zs = Bsf + 2 * H1_BK * H1_BN;                   // [16][16]

    int tid = threadIdx.x;
    int tx = tid & 15, ty = tid >> 4;
    int m0 = blockIdx.y * H1_BM, n0 = blockIdx.x * H1_BN;

    // z tile -> smem
    for (int e = tid; e < 256; e += 128) zs[e] = z[m0 * LATENT + e];
    __syncthreads();

    // fused h0: warp w covers c = lane + 32w + 128j
    {
        int w = tid >> 5, lane = tid & 31;
#pragma unroll
        for (int j = 0; j < 4; j++) {
            int c = lane + 32 * w + 128 * j;
            float hw0r[16];
#pragma unroll
            for (int k = 0; k < 16; k++) hw0r[k] = hw0[k * HID + c];
            float bb = hb0[c];
#pragma unroll
            for (int r = 0; r < 16; r++) {
                float acc = bb;
#pragma unroll
                for (int k = 0; k < 16; k++)
                    acc = fmaf(zs[r * 16 + k], hw0r[k], acc);
                acc = leaky(acc);
                Ad[c * H1_AD_STR + r] = pack2(acc, acc);
            }
        }
    }

    u64 acc[2][2];
#pragma unroll
    for (int i = 0; i < 2; i++)
#pragma unroll
        for (int j = 0; j < 2; j++) acc[i][j] = pack2(0.0f, 0.0f);

    float pb[8];
    int pbn = tid & 63, pbk0 = tid >> 6;

    auto ldg_b = [&](int k0) {
#pragma unroll
        for (int r = 0; r < 8; r++)
            pb[r] = B[(size_t)(k0 + pbk0 + r * 2) * HID + n0 + pbn];
    };
    auto sts_b = [&](int s) {
#pragma unroll
        for (int r = 0; r < 8; r++)
            Bsf[s * 1024 + (pbk0 + r * 2) * H1_BN + pbn] = pb[r];
    };

    ldg_b(0);
    sts_b(0);
    __syncthreads();

    int p = 0;
    for (int t = 0; t < HID / H1_BK; t++) {
        if (t + 1 < HID / H1_BK) ldg_b((t + 1) * H1_BK);
#pragma unroll
        for (int k = 0; k < H1_BK; k++) {
            int kk = t * H1_BK + k;
            u64 ra0 = Ad[kk * H1_AD_STR + ty * 2];
            u64 ra1 = Ad[kk * H1_AD_STR + ty * 2 + 1];
            u64 rb0 = *(const u64*)&Bsf[p * 1024 + k * H1_BN + tx * 2];
            u64 rb1 = *(const u64*)&Bsf[p * 1024 + k * H1_BN + tx * 2 + 32];
            fma2(acc[0][0], ra0, rb0); fma2(acc[0][1], ra0, rb1);
            fma2(acc[1][0], ra1, rb0); fma2(acc[1][1], ra1, rb1);
        }
        if (t + 1 < HID / H1_BK) {
            sts_b(p ^ 1);
            __syncthreads();
        }
        p ^= 1;
    }

#pragma unroll
    for (int i = 0; i < 2; i++) {
        int m = m0 + ty * 2 + i;
#pragma unroll
        for (int j = 0; j < 2; j++) {
            float lo, hi;
            asm("mov.b64 {%0, %1}, %2;" : "=f"(lo), "=f"(hi) : "l"(acc[i][j]));
            int n = n0 + tx * 2 + j * 32;
            float v0 = leaky(lo + bias[n]);
            float v1 = leaky(hi + bias[n + 1]);
            float h0f = __half2float(__float2half_rn(v0));
            float h1f = __half2float(__float2half_rn(v1));
            *(uint32_t*)&Ch[(size_t)m * HID + n] = packh2(h0f, h1f);
            *(uint32_t*)&Cl[(size_t)m * HID + n] = packh2(v0 - h0f, v1 - h1f);
        }
    }
}

// ---------------------------------------------------------------------------
// wb GEMM via fp16 mma (2-split), 132 CTAs x 256 threads, warp m64 x n24,
// double-buffered smem + ldmatrix fragment loads (BSTR=72, rotated B stores).
// ---------------------------------------------------------------------------
#define KT 32
#define BNW 96
#define ASTR 72
#define BSTR 72
#define STG_H (2 * 128 * ASTR + 2 * BNW * BSTR)   // halves per stage
#define WB_SMEM_BYTES (2 * STG_H * 2)

__global__ void __launch_bounds__(256)
k_wbgemm(const __half* __restrict__ Ah_g, const __half* __restrict__ Al_g,
         const float* __restrict__ Bg, const float* __restrict__ bias,
         float* __restrict__ Cout) {
    extern __shared__ __align__(16) __half smh[];
    uint32_t sb = smem_u32(smh);

    int tid = threadIdx.x;
    int lane = tid & 31;
    int wid = tid >> 5;
    int g4 = lane >> 2;
    int t4 = lane & 3;
    int wm = wid & 1;        // m-half (64 rows)
    int wn = wid >> 1;       // n-quarter (24 cols)
    int n0 = blockIdx.x * BNW;

    int bn = tid % BNW, bkh = tid / BNW;     // B staging: threads < 192
    bool bact = tid < 192;
    bool bok = bact && (n0 + bn) < OUTSZ;
    int brot = (bn >> 3) & 7;

    // ldmatrix row offsets (halves)
    int rA = (wm * 64 + (lane & 15)) * ASTR + (lane >> 4) * 8;
    int rB01 = (wn * 24 + (lane & 7) + ((lane >> 4) << 3)) * BSTR
             + ((lane >> 3) & 1) * 8;
    int rB2 = (wn * 24 + 16 + (lane & 7)) * BSTR + ((lane >> 3) & 1) * 8;

    float4 acc[4][3];
#pragma unroll
    for (int i = 0; i < 4; i++)
#pragma unroll
        for (int j = 0; j < 3; j++) acc[i][j] = make_float4(0.f, 0.f, 0.f, 0.f);

    u64 pah[4], pal[4];
    float pb[16];

    auto ldg_tile = [&](int kt) {
#pragma unroll
        for (int i = 0; i < 4; i++) {
            int idx = tid + i * 256;          // 1024 u64 slots (128 rows x 8)
            int m = idx >> 3, j = idx & 7;
            pah[i] = *(const u64*)&Ah_g[(size_t)m * HID + kt + j * 4];
            pal[i] = *(const u64*)&Al_g[(size_t)m * HID + kt + j * 4];
        }
        if (bact) {
            const float* bp = Bg + (size_t)(kt + bkh * 16) * OUTSZ + n0 + bn;
#pragma unroll
            for (int j = 0; j < 16; j++)
                pb[j] = bok ? bp[(size_t)j * OUTSZ] : 0.0f;
        }
    };
    auto sts_tile = [&](int s) {
        __half* As_h = smh + s * STG_H;
        __half* As_l = As_h + 128 * ASTR;
        __half* Bs_h = As_l + 128 * ASTR;
        __half* Bs_l = Bs_h + BNW * BSTR;
#pragma unroll
        for (int i = 0; i < 4; i++) {
            int idx = tid + i * 256;
            int m = idx >> 3, j = idx & 7;
            *(u64*)&As_h[m * ASTR + j * 4] = pah[i];
            *(u64*)&As_l[m * ASTR + j * 4] = pal[i];
        }
        if (bact) {
#pragma unroll
            for (int s2 = 0; s2 < 8; s2++) {
                int jr = (s2 + brot) & 7;            // rotated store order
                float v0 = pb[2 * jr], v1 = pb[2 * jr + 1];
                float h0 = __half2float(__float2half_rn(v0));
                float h1 = __half2float(__float2half_rn(v1));
                *(uint32_t*)&Bs_h[bn * BSTR + bkh * 16 + 2 * jr] = packh2(h0, h1);
                *(uint32_t*)&Bs_l[bn * BSTR + bkh * 16 + 2 * jr] =
                    packh2(v0 - h0, v1 - h1);
            }
        }
    };

    ldg_tile(0);
    sts_tile(0);
    __syncthreads();

    int p = 0;
    for (int t = 0; t < HID / KT; t++) {
        if (t + 1 < HID / KT) ldg_tile((t + 1) * KT);

        uint32_t bAh = sb + 2 * (p * STG_H);
        uint32_t bAl = bAh + 2 * 128 * ASTR;
        uint32_t bBh = bAl + 2 * 128 * ASTR;
        uint32_t bBl = bBh + 2 * BNW * BSTR;

#pragma unroll
        for (int ks = 0; ks < KT; ks += 16) {
            uint32_t ah[4][4], al[4][4];
#pragma unroll
            for (int mf = 0; mf < 4; mf++) {
                ldsm4(ah[mf], bAh + 2 * (rA + mf * 16 * ASTR + ks));
                ldsm4(al[mf], bAl + 2 * (rA + mf * 16 * ASTR + ks));
            }
            uint32_t b01h[4], b01l[4], b2h[2], b2l[2];
            ldsm4(b01h, bBh + 2 * (rB01 + ks));
            ldsm4(b01l, bBl + 2 * (rB01 + ks));
            ldsm2(b2h, bBh + 2 * (rB2 + ks));
            ldsm2(b2l, bBl + 2 * (rB2 + ks));
#pragma unroll
            for (int mf = 0; mf < 4; mf++) {
                mma_f16(acc[mf][0], ah[mf], b01h);
                mma_f16(acc[mf][0], ah[mf], b01l);
                mma_f16(acc[mf][0], al[mf], b01h);
                mma_f16(acc[mf][1], ah[mf], b01h + 2);
                mma_f16(acc[mf][1], ah[mf], b01l + 2);
                mma_f16(acc[mf][1], al[mf], b01h + 2);
                mma_f16(acc[mf][2], ah[mf], b2h);
                mma_f16(acc[mf][2], ah[mf], b2l);
                mma_f16(acc[mf][2], al[mf], b2h);
            }
        }
        if (t + 1 < HID / KT) {
            sts_tile(p ^ 1);
            __syncthreads();
        }
        p ^= 1;
    }

    // epilogue: bias + permuted scatter
#pragma unroll
    for (int mf = 0; mf < 4; mf++) {
        int m = wm * 64 + mf * 16 + g4;
#pragma unroll
        for (int nf = 0; nf < 3; nf++) {
            int n = n0 + wn * 24 + nf * 8 + t4 * 2;
            if (n < OUTSZ) {
                Cout[(size_t)m * OUTSZ_PAD + perm_wb(n)] = acc[mf][nf].x + bias[n];
                Cout[(size_t)(m + 8) * OUTSZ_PAD + perm_wb(n)] = acc[mf][nf].z + bias[n];
            }
            if (n + 1 < OUTSZ) {
                Cout[(size_t)m * OUTSZ_PAD + perm_wb(n + 1)] = acc[mf][nf].y + bias[n + 1];
                Cout[(size_t)(m + 8) * OUTSZ_PAD + perm_wb(n + 1)] = acc[mf][nf].w + bias[n + 1];
            }
        }
    }
}

// ---------------------------------------------------------------------------
// Decoder via fp16 mma (2-split), 512 threads (16 warps: wm 0..7 m16,
// wn 0..1 n32), ldmatrix fragment loads + next-layer W prefetch.
// X fp16 [m][72]; W transposed fp16 [n][72].
// ---------------------------------------------------------------------------
#define XSH 72
#define WSH 72
#define XBUFH (NG * XSH)          // 9216 halves
#define WBUFH (DD * WSH)          // 4608 halves
#define DEC_SMEM_BYTES ((4 * XBUFH + 2 * WBUFH) * 2 + 512 * 4)

__global__ void __launch_bounds__(512)
k_decode(const float* __restrict__ logP, float* __restrict__ out) {
    extern __shared__ __align__(16) __half smh[];
    __half* XAh = smh;
    __half* XAl = smh + XBUFH;
    __half* XBh = smh + 2 * XBUFH;
    __half* XBl = smh + 3 * XBUFH;
    __half* Wth = smh + 4 * XBUFH;
    __half* Wtl = smh + 4 * XBUFH + WBUFH;
    float* part = (float*)(smh + 4 * XBUFH + 2 * WBUFH);
    uint32_t sb = smem_u32(smh);
    uint32_t bXA_h = sb, bXA_l = sb + 2 * XBUFH;
    uint32_t bXB_h = sb + 4 * XBUFH, bXB_l = sb + 6 * XBUFH;
    uint32_t bW_h = sb + 8 * XBUFH, bW_l = bW_h + 2 * WBUFH;

    int b = blockIdx.x;
    int tid = threadIdx.x;
    int lane = tid & 31;
    int wid = tid >> 5;
    int g4 = lane >> 2;
    int t4 = lane & 3;
    int wm = wid & 7;          // m-sixteenth (16 rows)
    int wn = wid >> 3;         // n-half (32 cols)
    const float* brow = g_wb + (size_t)b * OUTSZ_PAD;

    // ldmatrix row offsets (halves)
    int rX = (wm * 16 + (lane & 15)) * XSH + (lane >> 4) * 8;
    int rW01 = (wn * 32 + (lane & 7) + ((lane >> 4) << 3)) * WSH
             + ((lane >> 3) & 1) * 8;
    int rW23 = rW01 + 16 * WSH;

    // W layer-0 prefetch (issued before the sin-heavy first layer)
    int wsi = tid >> 3, wsj0 = (tid & 7) * 8;
    int wsrot = tid & 7;
    float wv[8];
    {
        const float* Wg = brow;
        float4 wa = *(const float4*)&Wg[wsi * DD + wsj0];
        float4 wb4 = *(const float4*)&Wg[wsi * DD + wsj0 + 4];
        wv[0] = wa.x; wv[1] = wa.y; wv[2] = wa.z; wv[3] = wa.w;
        wv[4] = wb4.x; wv[5] = wb4.y; wv[6] = wb4.z; wv[7] = wb4.w;
    }

    // ---- first layer: X0 = sin(30*(xin*W0 + b0)), fp16 hi/lo, rotated ----
    {
        int g = tid & (NG - 1);
        int q = tid >> 7;                    // 0..3
        int rot = (g >> 3) & 7;
        float xin = logP[b * NG + g];
        float b0v = brow[12608];
#pragma unroll
        for (int s = 0; s < 8; s++) {
            int j = q * 16 + 2 * ((s + rot) & 7);
            float v0 = fsin(30.0f * fmaf(xin, brow[OFF_W0 + j], b0v));
            float v1 = fsin(30.0f * fmaf(xin, brow[OFF_W0 + j + 1], b0v));
            float h0 = __half2float(__float2half_rn(v0));
            float h1 = __half2float(__float2half_rn(v1));
            *(uint32_t*)&XAh[g * XSH + j] = packh2(h0, h1);
            *(uint32_t*)&XAl[g * XSH + j] = packh2(v0 - h0, v1 - h1);
        }
    }
    __syncthreads();

#pragma unroll 1
    for (int it = 0; it < 3; it++) {
        // stage W (transposed, rotated store order)
#pragma unroll
        for (int s = 0; s < 8; s++) {
            int jj = (s + wsrot) & 7;
            int j = wsj0 + jj;
            float hf = __half2float(__float2half_rn(wv[jj]));
            Wth[j * WSH + wsi] = __float2half_rn(hf);
            Wtl[j * WSH + wsi] = __float2half_rn(wv[jj] - hf);
        }
        float biasE[4], biasO[4];
#pragma unroll
        for (int nf = 0; nf < 4; nf++) {
            int col = wn * 32 + nf * 8 + 2 * t4;
            biasE[nf] = brow[OFF_B + it * DD + col];
            biasO[nf] = brow[OFF_B + it * DD + col + 1];
        }
        __syncthreads();

        // prefetch next layer's W (overlaps MMA below)
        float wvn[8];
        if (it < 2) {
            const float* Wg = brow + (it + 1) * DD * DD;
            float4 wa = *(const float4*)&Wg[wsi * DD + wsj0];
            float4 wb4 = *(const float4*)&Wg[wsi * DD + wsj0 + 4];
            wvn[0] = wa.x; wvn[1] = wa.y; wvn[2] = wa.z; wvn[3] = wa.w;
            wvn[4] = wb4.x; wvn[5] = wb4.y; wvn[6] = wb4.z; wvn[7] = wb4.w;
        }

        uint32_t bXh = (it & 1) ? bXB_h : bXA_h;
        uint32_t bXl = (it & 1) ? bXB_l : bXA_l;
        __half* Xoh = (it & 1) ? XAh : XBh;
        __half* Xol = (it & 1) ? XAl : XBl;

        float4 acc[4];
#pragma unroll
        for (int nf = 0; nf < 4; nf++)
            acc[nf] = make_float4(biasE[nf], biasO[nf], biasE[nf], biasO[nf]);

        int m = wm * 16 + g4;
#pragma unroll
        for (int k16 = 0; k16 < DD; k16 += 16) {
            uint32_t ah[4], al[4];
            ldsm4(ah, bXh + 2 * (rX + k16));
            ldsm4(al, bXl + 2 * (rX + k16));
            uint32_t b01h[4], b01l[4], b23h[4], b23l[4];
            ldsm4(b01h, bW_h + 2 * (rW01 + k16));
            ldsm4(b01l, bW_l + 2 * (rW01 + k16));
            ldsm4(b23h, bW_h + 2 * (rW23 + k16));
            ldsm4(b23l, bW_l + 2 * (rW23 + k16));
            mma_f16(acc[0], ah, b01h);
            mma_f16(acc[0], ah, b01l);
            mma_f16(acc[0], al, b01h);
            mma_f16(acc[1], ah, b01h + 2);
            mma_f16(acc[1], ah, b01l + 2);
            mma_f16(acc[1], al, b01h + 2);
            mma_f16(acc[2], ah, b23h);
            mma_f16(acc[2], ah, b23l);
            mma_f16(acc[2], al, b23h);
            mma_f16(acc[3], ah, b23h + 2);
            mma_f16(acc[3], ah, b23l + 2);
            mma_f16(acc[3], al, b23h + 2);
        }

        // sin + split + store (c0,c1 -> row m; c2,c3 -> row m+8)
#pragma unroll
        for (int nf = 0; nf < 4; nf++) {
            int col = wn * 32 + nf * 8 + 2 * t4;
            float4 a = acc[nf];
            float v0 = fsin(a.x), v1 = fsin(a.y);
            float v2 = fsin(a.z), v3 = fsin(a.w);
            float h0 = __half2float(__float2half_rn(v0));
            float h1 = __half2float(__float2half_rn(v1));
            float h2 = __half2float(__float2half_rn(v2));
            float h3 = __half2float(__float2half_rn(v3));
            *(uint32_t*)&Xoh[m * XSH + col] = packh2(h0, h1);
            *(uint32_t*)&Xol[m * XSH + col] = packh2(v0 - h0, v1 - h1);
            *(uint32_t*)&Xoh[(m + 8) * XSH + col] = packh2(h2, h3);
            *(uint32_t*)&Xol[(m + 8) * XSH + col] = packh2(v2 - h2, v3 - h3);
        }
        __syncthreads();
#pragma unroll
        for (int q = 0; q < 8; q++) wv[q] = wvn[q];
    }

    // ---- final layer: out[g] = (X3 . W4) + b4 (X3 in XB after it=2) ----
    {
        int g = tid & (NG - 1);
        int q = tid >> 7;
        float s = 0.0f;
#pragma unroll
        for (int ii = 0; ii < 16; ii++) {
            int i = q * 16 + ii;
            float xv = __half2float(XBh[g * XSH + i]) + __half2float(XBl[g * XSH + i]);
            s = fmaf(xv, brow[OFF_W4 + i], s);
        }
        part[q * NG + g] = s;
    }
    __syncthreads();
    if (tid < NG) {
        float acc = brow[12609] + part[tid] + part[NG + tid]
                  + part[2 * NG + tid] + part[3 * NG + tid];
        out[b * NG + tid] = fmaf(acc, 500.0f, 1500.0f);
    }
}

// ---------------------------------------------------------------------------
extern "C" void kernel_launch(void* const* d_in, const int* in_sizes, int n_in,
                              void* d_out, int out_size) {
    (void)in_sizes; (void)n_in; (void)out_size;
    const float* z    = (const float*)d_in[0];
    const float* logP = (const float*)d_in[1];
    const float* hw0  = (const float*)d_in[2];
    const float* hb0  = (const float*)d_in[3];
    const float* hw1  = (const float*)d_in[4];
    const float* hb1  = (const float*)d_in[5];
    const float* hw2  = (const float*)d_in[6];
    const float* hb2  = (const float*)d_in[7];
    float* out = (float*)d_out;

    float* p_wb;
    __half *p_h1h, *p_h1l;
    cudaGetSymbolAddress((void**)&p_h1h, g_h1h);
    cudaGetSymbolAddress((void**)&p_h1l, g_h1l);
    cudaGetSymbolAddress((void**)&p_wb, g_wb);

    cudaFuncSetAttribute(gemm_h1, cudaFuncAttributeMaxDynamicSharedMemorySize,
                         H1_SMEM_BYTES);
    cudaFuncSetAttribute(k_wbgemm, cudaFuncAttributeMaxDynamicSharedMemorySize,
                         WB_SMEM_BYTES);
    cudaFuncSetAttribute(k_decode, cudaFuncAttributeMaxDynamicSharedMemorySize,
                         DEC_SMEM_BYTES);

    // 1) h1 = leaky(leaky(z@hw0+hb0) @ hw1 + hb1), fused h0, fp16 split out
    {
        dim3 grid(HID / H1_BN, NB / H1_BM);   // 64 blocks
        gemm_h1<<<grid, 128, H1_SMEM_BYTES>>>(z, hw0, hb0, hw1, hb1,
                                              p_h1h, p_h1l);
    }

    // 2) wb = h1 @ hw2 + hb2 via fp16 mma (2-split), ldmatrix, 132 CTAs
    k_wbgemm<<<(OUTSZ + BNW - 1) / BNW, 256, WB_SMEM_BYTES>>>(
        p_h1h, p_h1l, hw2, hb2, p_wb);

    // 3) decoder on tensor cores (fp16 2-split, ldmatrix)
    k_decode<<<NB, 512, DEC_SMEM_BYTES>>>(logP, out);
}

// round 15
// speedup vs baseline: 1.3331x; 1.1591x over previous
#include <cuda_runtime.h>
#include <cuda_fp16.h>
#include <cstdint>

#define LATENT 16
#define HID 512
#define DD 64
#define NB 128
#define NG 128
#define OUTSZ 12610
#define OUTSZ_PAD 12612

// Scratch (device globals — no allocation allowed)
__device__ float g_h1p[4 * NB * HID];  // split-K partials of h1
__device__ __half g_h1h[NB * HID];     // fp16-hi split of h1, [m][k]
__device__ __half g_h1l[NB * HID];     // fp16-lo split of h1, [m][k]
__device__ float g_wb[NB * OUTSZ_PAD]; // PRE-PERMUTED into decoder layout

typedef unsigned long long u64;

__device__ __forceinline__ u64 pack2(float lo, float hi) {
    u64 r; asm("mov.b64 %0, {%1, %2};" : "=l"(r) : "f"(lo), "f"(hi)); return r;
}
__device__ __forceinline__ void fma2(u64& d, u64 a, u64 b) {
    asm("fma.rn.f32x2 %0, %1, %2, %0;" : "+l"(d) : "l"(a), "l"(b));
}

__device__ __forceinline__ float leaky(float x) { return x > 0.0f ? x : 0.01f * x; }

// fast sin: 2-step Cody-Waite range reduction + MUFU sin (args stay < ~40)
__device__ __forceinline__ float fsin(float x) {
    float k = rintf(x * 0.15915494309189535f);
    x = fmaf(k, -6.28125f, x);
    x = fmaf(k, -1.9353071795864769e-3f, x);
    return __sinf(x);
}

// pack two fp32 into one u32 of 2 fp16 (lo half = first arg)
__device__ __forceinline__ uint32_t packh2(float vlo, float vhi) {
    uint32_t d;
    asm("cvt.rn.f16x2.f32 %0, %1, %2;" : "=r"(d) : "f"(vhi), "f"(vlo));
    return d;
}

__device__ __forceinline__ uint32_t smem_u32(const void* p) {
    uint32_t a;
    asm("{ .reg .u64 t; cvta.to.shared.u64 t, %1; cvt.u32.u64 %0, t; }"
        : "=r"(a) : "l"(p));
    return a;
}

// ldmatrix: 4 / 2 8x8 b16 matrices per warp-collective instruction
__device__ __forceinline__ void ldsm4(uint32_t* r, uint32_t a) {
    asm volatile("ldmatrix.sync.aligned.m8n8.x4.shared.b16 {%0,%1,%2,%3}, [%4];"
                 : "=r"(r[0]), "=r"(r[1]), "=r"(r[2]), "=r"(r[3]) : "r"(a));
}
__device__ __forceinline__ void ldsm2(uint32_t* r, uint32_t a) {
    asm volatile("ldmatrix.sync.aligned.m8n8.x2.shared.b16 {%0,%1}, [%2];"
                 : "=r"(r[0]), "=r"(r[1]) : "r"(a));
}

// fp16 mma m16n8k16 (fragment mappings validated rounds 10-14)
__device__ __forceinline__ void mma_f16(float4& c, const uint32_t a[4],
                                        const uint32_t b[2]) {
    asm volatile(
        "mma.sync.aligned.m16n8k16.row.col.f32.f16.f16.f32 "
        "{%0,%1,%2,%3}, {%4,%5,%6,%7}, {%8,%9}, {%0,%1,%2,%3};"
        : "+f"(c.x), "+f"(c.y), "+f"(c.z), "+f"(c.w)
        : "r"(a[0]), "r"(a[1]), "r"(a[2]), "r"(a[3]), "r"(b[0]), "r"(b[1]));
}

// Decoder layout (floats): W1[0,4096) W2[4096,8192) W3[8192,12288) W0[12288,12352)
// b1[12352,12416) b2[12416,12480) b3[12480,12544) W4[12544,12608) b0[12608] b4[12609]
#define OFF_W0 12288
#define OFF_B  12352
#define OFF_W4 12544

__device__ __forceinline__ int perm_wb(int n) {
    if (n < 4161)  return (n < 64) ? 12288 + n : (n == 64 ? 12608 : n - 65);
    if (n < 8321)  return (n < 4225) ? 12352 + (n - 4161) : 4096 + (n - 4225);
    if (n < 12481) return (n < 8385) ? 12416 + (n - 8321) : 8192 + (n - 8385);
    if (n < 12545) return 12480 + (n - 12481);
    return (n < 12609) ? 12544 + (n - 12545) : 12609;
}

// ---------------------------------------------------------------------------
// h1 split-K GEMM with lean fused h0. Grid (8 n-tiles, 8 m-tiles, 4 k-chunks)
// = 256 CTAs x 128 thr. Each CTA: computes its 16x128 h0 chunk into dup-u64
// smem, then 8 double-buffered FFMA iterations over K-chunk 128.
// Writes raw fp32 partials (bias/leaky applied in reduce).
// ---------------------------------------------------------------------------
#define H1_AD_STR 17

__global__ void __launch_bounds__(128)
k_h1split(const float* __restrict__ z, const float* __restrict__ hw0,
          const float* __restrict__ hb0, const float* __restrict__ hw1,
          float* __restrict__ partial) {
    __shared__ __align__(16) u64 Ad[128 * H1_AD_STR];  // [k_local][m] dup h0
    __shared__ __align__(16) float Bs[2][16][64];
    __shared__ float zs[256];

    int tid = threadIdx.x;
    int tx = tid & 15, ty = tid >> 4;
    int n0 = blockIdx.x * 64;
    int m0 = blockIdx.y * 16;
    int kbase = blockIdx.z * 128;

    // z tile -> smem
    for (int e = tid; e < 256; e += 128) zs[e] = z[m0 * LATENT + e];
    __syncthreads();

    // fused h0 chunk: this thread owns column c = kbase + tid (k_local = tid)
    {
        int cg = kbase + tid;
        float hw0r[16];
#pragma unroll
        for (int k = 0; k < 16; k++) hw0r[k] = hw0[k * HID + cg];
        float bb = hb0[cg];
#pragma unroll
        for (int r = 0; r < 16; r++) {
            float acc = bb;
#pragma unroll
            for (int k = 0; k < 16; k++) acc = fmaf(zs[r * 16 + k], hw0r[k], acc);
            acc = leaky(acc);
            Ad[tid * H1_AD_STR + r] = pack2(acc, acc);
        }
    }

    u64 acc[2][2];
#pragma unroll
    for (int i = 0; i < 2; i++)
#pragma unroll
        for (int j = 0; j < 2; j++) acc[i][j] = pack2(0.0f, 0.0f);

    float pb[8];
    int pbn = tid & 63, pbk0 = tid >> 6;

    auto ldg_b = [&](int k0) {
#pragma unroll
        for (int r = 0; r < 8; r++)
            pb[r] = hw1[(size_t)(k0 + pbk0 + r * 2) * HID + n0 + pbn];
    };
    auto sts_b = [&](int s) {
#pragma unroll
        for (int r = 0; r < 8; r++) Bs[s][pbk0 + r * 2][pbn] = pb[r];
    };

    ldg_b(kbase);
    sts_b(0);
    __syncthreads();   // also covers Ad writes

    int p = 0;
    for (int t = 0; t < 8; t++) {
        if (t + 1 < 8) ldg_b(kbase + (t + 1) * 16);
#pragma unroll
        for (int k = 0; k < 16; k++) {
            int kk = t * 16 + k;
            u64 ra0 = Ad[kk * H1_AD_STR + ty * 2];
            u64 ra1 = Ad[kk * H1_AD_STR + ty * 2 + 1];
            u64 rb0 = *(const u64*)&Bs[p][k][tx * 2];
            u64 rb1 = *(const u64*)&Bs[p][k][tx * 2 + 32];
            fma2(acc[0][0], ra0, rb0); fma2(acc[0][1], ra0, rb1);
            fma2(acc[1][0], ra1, rb0); fma2(acc[1][1], ra1, rb1);
        }
        if (t + 1 < 8) {
            sts_b(p ^ 1);
            __syncthreads();
        }
        p ^= 1;
    }

    // raw partial store
    float* outp = partial + (size_t)blockIdx.z * (NB * HID);
#pragma unroll
    for (int i = 0; i < 2; i++) {
        int m = m0 + ty * 2 + i;
#pragma unroll
        for (int j = 0; j < 2; j++) {
            float lo, hi;
            asm("mov.b64 {%0, %1}, %2;" : "=f"(lo), "=f"(hi) : "l"(acc[i][j]));
            int n = n0 + tx * 2 + j * 32;
            outp[(size_t)m * HID + n] = lo;
            outp[(size_t)m * HID + n + 1] = hi;
        }
    }
}

// ---------------------------------------------------------------------------
// h1 reduce: sum 4 partials + bias + leaky + fp16 hi/lo split.
// 32 CTAs x 1024 threads, each thread one (m, n-pair).
// ---------------------------------------------------------------------------
__global__ void __launch_bounds__(1024)
k_h1red(const float* __restrict__ partial, const float* __restrict__ bias,
        __half* __restrict__ Ch, __half* __restrict__ Cl) {
    int p = blockIdx.x * 1024 + threadIdx.x;  // 0..32767
    int m = p >> 8;
    int n = (p & 255) * 2;
    const float* base = partial + (size_t)m * HID + n;
    float2 s0 = *(const float2*)(base);
    float2 s1 = *(const float2*)(base + NB * HID);
    float2 s2 = *(const float2*)(base + 2 * NB * HID);
    float2 s3 = *(const float2*)(base + 3 * NB * HID);
    float v0 = leaky(s0.x + s1.x + s2.x + s3.x + bias[n]);
    float v1 = leaky(s0.y + s1.y + s2.y + s3.y + bias[n + 1]);
    float h0f = __half2float(__float2half_rn(v0));
    float h1f = __half2float(__float2half_rn(v1));
    *(uint32_t*)&Ch[(size_t)m * HID + n] = packh2(h0f, h1f);
    *(uint32_t*)&Cl[(size_t)m * HID + n] = packh2(v0 - h0f, v1 - h1f);
}

// ---------------------------------------------------------------------------
// wb GEMM via fp16 mma (2-split), 132 CTAs x 256 threads, warp m64 x n24,
// double-buffered smem + ldmatrix fragment loads (BSTR=72, rotated B stores).
// ---------------------------------------------------------------------------
#define KT 32
#define BNW 96
#define ASTR 72
#define BSTR 72
#define STG_H (2 * 128 * ASTR + 2 * BNW * BSTR)   // halves per stage
#define WB_SMEM_BYTES (2 * STG_H * 2)

__global__ void __launch_bounds__(256)
k_wbgemm(const __half* __restrict__ Ah_g, const __half* __restrict__ Al_g,
         const float* __restrict__ Bg, const float* __restrict__ bias,
         float* __restrict__ Cout) {
    extern __shared__ __align__(16) __half smh[];
    uint32_t sb = smem_u32(smh);

    int tid = threadIdx.x;
    int lane = tid & 31;
    int wid = tid >> 5;
    int g4 = lane >> 2;
    int t4 = lane & 3;
    int wm = wid & 1;        // m-half (64 rows)
    int wn = wid >> 1;       // n-quarter (24 cols)
    int n0 = blockIdx.x * BNW;

    int bn = tid % BNW, bkh = tid / BNW;     // B staging: threads < 192
    bool bact = tid < 192;
    bool bok = bact && (n0 + bn) < OUTSZ;
    int brot = (bn >> 3) & 7;

    // ldmatrix row offsets (halves)
    int rA = (wm * 64 + (lane & 15)) * ASTR + (lane >> 4) * 8;
    int rB01 = (wn * 24 + (lane & 7) + ((lane >> 4) << 3)) * BSTR
             + ((lane >> 3) & 1) * 8;
    int rB2 = (wn * 24 + 16 + (lane & 7)) * BSTR + ((lane >> 3) & 1) * 8;

    float4 acc[4][3];
#pragma unroll
    for (int i = 0; i < 4; i++)
#pragma unroll
        for (int j = 0; j < 3; j++) acc[i][j] = make_float4(0.f, 0.f, 0.f, 0.f);

    u64 pah[4], pal[4];
    float pb[16];

    auto ldg_tile = [&](int kt) {
#pragma unroll
        for (int i = 0; i < 4; i++) {
            int idx = tid + i * 256;          // 1024 u64 slots (128 rows x 8)
            int m = idx >> 3, j = idx & 7;
            pah[i] = *(const u64*)&Ah_g[(size_t)m * HID + kt + j * 4];
            pal[i] = *(const u64*)&Al_g[(size_t)m * HID + kt + j * 4];
        }
        if (bact) {
            const float* bp = Bg + (size_t)(kt + bkh * 16) * OUTSZ + n0 + bn;
#pragma unroll
            for (int j = 0; j < 16; j++)
                pb[j] = bok ? bp[(size_t)j * OUTSZ] : 0.0f;
        }
    };
    auto sts_tile = [&](int s) {
        __half* As_h = smh + s * STG_H;
        __half* As_l = As_h + 128 * ASTR;
        __half* Bs_h = As_l + 128 * ASTR;
        __half* Bs_l = Bs_h + BNW * BSTR;
#pragma unroll
        for (int i = 0; i < 4; i++) {
            int idx = tid + i * 256;
            int m = idx >> 3, j = idx & 7;
            *(u64*)&As_h[m * ASTR + j * 4] = pah[i];
            *(u64*)&As_l[m * ASTR + j * 4] = pal[i];
        }
        if (bact) {
#pragma unroll
            for (int s2 = 0; s2 < 8; s2++) {
                int jr = (s2 + brot) & 7;            // rotated store order
                float v0 = pb[2 * jr], v1 = pb[2 * jr + 1];
                float h0 = __half2float(__float2half_rn(v0));
                float h1 = __half2float(__float2half_rn(v1));
                *(uint32_t*)&Bs_h[bn * BSTR + bkh * 16 + 2 * jr] = packh2(h0, h1);
                *(uint32_t*)&Bs_l[bn * BSTR + bkh * 16 + 2 * jr] =
                    packh2(v0 - h0, v1 - h1);
            }
        }
    };

    ldg_tile(0);
    sts_tile(0);
    __syncthreads();

    int p = 0;
    for (int t = 0; t < HID / KT; t++) {
        if (t + 1 < HID / KT) ldg_tile((t + 1) * KT);

        uint32_t bAh = sb + 2 * (p * STG_H);
        uint32_t bAl = bAh + 2 * 128 * ASTR;
        uint32_t bBh = bAl + 2 * 128 * ASTR;
        uint32_t bBl = bBh + 2 * BNW * BSTR;

#pragma unroll
        for (int ks = 0; ks < KT; ks += 16) {
            uint32_t ah[4][4], al[4][4];
#pragma unroll
            for (int mf = 0; mf < 4; mf++) {
                ldsm4(ah[mf], bAh + 2 * (rA + mf * 16 * ASTR + ks));
                ldsm4(al[mf], bAl + 2 * (rA + mf * 16 * ASTR + ks));
            }
            uint32_t b01h[4], b01l[4], b2h[2], b2l[2];
            ldsm4(b01h, bBh + 2 * (rB01 + ks));
            ldsm4(b01l, bBl + 2 * (rB01 + ks));
            ldsm2(b2h, bBh + 2 * (rB2 + ks));
            ldsm2(b2l, bBl + 2 * (rB2 + ks));
#pragma unroll
            for (int mf = 0; mf < 4; mf++) {
                mma_f16(acc[mf][0], ah[mf], b01h);
                mma_f16(acc[mf][0], ah[mf], b01l);
                mma_f16(acc[mf][0], al[mf], b01h);
                mma_f16(acc[mf][1], ah[mf], b01h + 2);
                mma_f16(acc[mf][1], ah[mf], b01l + 2);
                mma_f16(acc[mf][1], al[mf], b01h + 2);
                mma_f16(acc[mf][2], ah[mf], b2h);
                mma_f16(acc[mf][2], ah[mf], b2l);
                mma_f16(acc[mf][2], al[mf], b2h);
            }
        }
        if (t + 1 < HID / KT) {
            sts_tile(p ^ 1);
            __syncthreads();
        }
        p ^= 1;
    }

    // epilogue: bias + permuted scatter
#pragma unroll
    for (int mf = 0; mf < 4; mf++) {
        int m = wm * 64 + mf * 16 + g4;
#pragma unroll
        for (int nf = 0; nf < 3; nf++) {
            int n = n0 + wn * 24 + nf * 8 + t4 * 2;
            if (n < OUTSZ) {
                Cout[(size_t)m * OUTSZ_PAD + perm_wb(n)] = acc[mf][nf].x + bias[n];
                Cout[(size_t)(m + 8) * OUTSZ_PAD + perm_wb(n)] = acc[mf][nf].z + bias[n];
            }
            if (n + 1 < OUTSZ) {
                Cout[(size_t)m * OUTSZ_PAD + perm_wb(n + 1)] = acc[mf][nf].y + bias[n + 1];
                Cout[(size_t)(m + 8) * OUTSZ_PAD + perm_wb(n + 1)] = acc[mf][nf].w + bias[n + 1];
            }
        }
    }
}

// ---------------------------------------------------------------------------
// Decoder via fp16 mma (2-split), 512 threads (16 warps: wm 0..7 m16,
// wn 0..1 n32), ldmatrix fragment loads + next-layer W prefetch.
// X fp16 [m][72]; W transposed fp16 [n][72].
// ---------------------------------------------------------------------------
#define XSH 72
#define WSH 72
#define XBUFH (NG * XSH)          // 9216 halves
#define WBUFH (DD * WSH)          // 4608 halves
#define DEC_SMEM_BYTES ((4 * XBUFH + 2 * WBUFH) * 2 + 512 * 4)

__global__ void __launch_bounds__(512)
k_decode(const float* __restrict__ logP, float* __restrict__ out) {
    extern __shared__ __align__(16) __half smh[];
    __half* XAh = smh;
    __half* XAl = smh + XBUFH;
    __half* XBh = smh + 2 * XBUFH;
    __half* XBl = smh + 3 * XBUFH;
    __half* Wth = smh + 4 * XBUFH;
    __half* Wtl = smh + 4 * XBUFH + WBUFH;
    float* part = (float*)(smh + 4 * XBUFH + 2 * WBUFH);
    uint32_t sb = smem_u32(smh);
    uint32_t bXA_h = sb, bXA_l = sb + 2 * XBUFH;
    uint32_t bXB_h = sb + 4 * XBUFH, bXB_l = sb + 6 * XBUFH;
    uint32_t bW_h = sb + 8 * XBUFH, bW_l = bW_h + 2 * WBUFH;

    int b = blockIdx.x;
    int tid = threadIdx.x;
    int lane = tid & 31;
    int wid = tid >> 5;
    int g4 = lane >> 2;
    int t4 = lane & 3;
    int wm = wid & 7;          // m-sixteenth (16 rows)
    int wn = wid >> 3;         // n-half (32 cols)
    const float* brow = g_wb + (size_t)b * OUTSZ_PAD;

    // ldmatrix row offsets (halves)
    int rX = (wm * 16 + (lane & 15)) * XSH + (lane >> 4) * 8;
    int rW01 = (wn * 32 + (lane & 7) + ((lane >> 4) << 3)) * WSH
             + ((lane >> 3) & 1) * 8;
    int rW23 = rW01 + 16 * WSH;

    // W layer-0 prefetch (issued before the sin-heavy first layer)
    int wsi = tid >> 3, wsj0 = (tid & 7) * 8;
    int wsrot = tid & 7;
    float wv[8];
    {
        const float* Wg = brow;
        float4 wa = *(const float4*)&Wg[wsi * DD + wsj0];
        float4 wb4 = *(const float4*)&Wg[wsi * DD + wsj0 + 4];
        wv[0] = wa.x; wv[1] = wa.y; wv[2] = wa.z; wv[3] = wa.w;
        wv[4] = wb4.x; wv[5] = wb4.y; wv[6] = wb4.z; wv[7] = wb4.w;
    }

    // ---- first layer: X0 = sin(30*(xin*W0 + b0)), fp16 hi/lo, rotated ----
    {
        int g = tid & (NG - 1);
        int q = tid >> 7;                    // 0..3
        int rot = (g >> 3) & 7;
        float xin = logP[b * NG + g];
        float b0v = brow[12608];
#pragma unroll
        for (int s = 0; s < 8; s++) {
            int j = q * 16 + 2 * ((s + rot) & 7);
            float v0 = fsin(30.0f * fmaf(xin, brow[OFF_W0 + j], b0v));
            float v1 = fsin(30.0f * fmaf(xin, brow[OFF_W0 + j + 1], b0v));
            float h0 = __half2float(__float2half_rn(v0));
            float h1 = __half2float(__float2half_rn(v1));
            *(uint32_t*)&XAh[g * XSH + j] = packh2(h0, h1);
            *(uint32_t*)&XAl[g * XSH + j] = packh2(v0 - h0, v1 - h1);
        }
    }
    __syncthreads();

#pragma unroll 1
    for (int it = 0; it < 3; it++) {
        // stage W (transposed, rotated store order)
#pragma unroll
        for (int s = 0; s < 8; s++) {
            int jj = (s + wsrot) & 7;
            int j = wsj0 + jj;
            float hf = __half2float(__float2half_rn(wv[jj]));
            Wth[j * WSH + wsi] = __float2half_rn(hf);
            Wtl[j * WSH + wsi] = __float2half_rn(wv[jj] - hf);
        }
        float biasE[4], biasO[4];
#pragma unroll
        for (int nf = 0; nf < 4; nf++) {
            int col = wn * 32 + nf * 8 + 2 * t4;
            biasE[nf] = brow[OFF_B + it * DD + col];
            biasO[nf] = brow[OFF_B + it * DD + col + 1];
        }
        __syncthreads();

        // prefetch next layer's W (overlaps MMA below)
        float wvn[8];
        if (it < 2) {
            const float* Wg = brow + (it + 1) * DD * DD;
            float4 wa = *(const float4*)&Wg[wsi * DD + wsj0];
            float4 wb4 = *(const float4*)&Wg[wsi * DD + wsj0 + 4];
            wvn[0] = wa.x; wvn[1] = wa.y; wvn[2] = wa.z; wvn[3] = wa.w;
            wvn[4] = wb4.x; wvn[5] = wb4.y; wvn[6] = wb4.z; wvn[7] = wb4.w;
        }

        uint32_t bXh = (it & 1) ? bXB_h : bXA_h;
        uint32_t bXl = (it & 1) ? bXB_l : bXA_l;
        __half* Xoh = (it & 1) ? XAh : XBh;
        __half* Xol = (it & 1) ? XAl : XBl;

        float4 acc[4];
#pragma unroll
        for (int nf = 0; nf < 4; nf++)
            acc[nf] = make_float4(biasE[nf], biasO[nf], biasE[nf], biasO[nf]);

        int m = wm * 16 + g4;
#pragma unroll
        for (int k16 = 0; k16 < DD; k16 += 16) {
            uint32_t ah[4], al[4];
            ldsm4(ah, bXh + 2 * (rX + k16));
            ldsm4(al, bXl + 2 * (rX + k16));
            uint32_t b01h[4], b01l[4], b23h[4], b23l[4];
            ldsm4(b01h, bW_h + 2 * (rW01 + k16));
            ldsm4(b01l, bW_l + 2 * (rW01 + k16));
            ldsm4(b23h, bW_h + 2 * (rW23 + k16));
            ldsm4(b23l, bW_l + 2 * (rW23 + k16));
            mma_f16(acc[0], ah, b01h);
            mma_f16(acc[0], ah, b01l);
            mma_f16(acc[0], al, b01h);
            mma_f16(acc[1], ah, b01h + 2);
            mma_f16(acc[1], ah, b01l + 2);
            mma_f16(acc[1], al, b01h + 2);
            mma_f16(acc[2], ah, b23h);
            mma_f16(acc[2], ah, b23l);
            mma_f16(acc[2], al, b23h);
            mma_f16(acc[3], ah, b23h + 2);
            mma_f16(acc[3], ah, b23l + 2);
            mma_f16(acc[3], al, b23h + 2);
        }

        // sin + split + store (c0,c1 -> row m; c2,c3 -> row m+8)
#pragma unroll
        for (int nf = 0; nf < 4; nf++) {
            int col = wn * 32 + nf * 8 + 2 * t4;
            float4 a = acc[nf];
            float v0 = fsin(a.x), v1 = fsin(a.y);
            float v2 = fsin(a.z), v3 = fsin(a.w);
            float h0 = __half2float(__float2half_rn(v0));
            float h1 = __half2float(__float2half_rn(v1));
            float h2 = __half2float(__float2half_rn(v2));
            float h3 = __half2float(__float2half_rn(v3));
            *(uint32_t*)&Xoh[m * XSH + col] = packh2(h0, h1);
            *(uint32_t*)&Xol[m * XSH + col] = packh2(v0 - h0, v1 - h1);
            *(uint32_t*)&Xoh[(m + 8) * XSH + col] = packh2(h2, h3);
            *(uint32_t*)&Xol[(m + 8) * XSH + col] = packh2(v2 - h2, v3 - h3);
        }
        __syncthreads();
#pragma unroll
        for (int q = 0; q < 8; q++) wv[q] = wvn[q];
    }

    // ---- final layer: out[g] = (X3 . W4) + b4 (X3 in XB after it=2) ----
    {
        int g = tid & (NG - 1);
        int q = tid >> 7;
        float s = 0.0f;
#pragma unroll
        for (int ii = 0; ii < 16; ii++) {
            int i = q * 16 + ii;
            float xv = __half2float(XBh[g * XSH + i]) + __half2float(XBl[g * XSH + i]);
            s = fmaf(xv, brow[OFF_W4 + i], s);
        }
        part[q * NG + g] = s;
    }
    __syncthreads();
    if (tid < NG) {
        float acc = brow[12609] + part[tid] + part[NG + tid]
                  + part[2 * NG + tid] + part[3 * NG + tid];
        out[b * NG + tid] = fmaf(acc, 500.0f, 1500.0f);
    }
}

// ---------------------------------------------------------------------------
extern "C" void kernel_launch(void* const* d_in, const int* in_sizes, int n_in,
                              void* d_out, int out_size) {
    (void)in_sizes; (void)n_in; (void)out_size;
    const float* z    = (const float*)d_in[0];
    const float* logP = (const float*)d_in[1];
    const float* hw0  = (const float*)d_in[2];
    const float* hb0  = (const float*)d_in[3];
    const float* hw1  = (const float*)d_in[4];
    const float* hb1  = (const float*)d_in[5];
    const float* hw2  = (const float*)d_in[6];
    const float* hb2  = (const float*)d_in[7];
    float* out = (float*)d_out;

    float *p_wb, *p_h1p;
    __half *p_h1h, *p_h1l;
    cudaGetSymbolAddress((void**)&p_h1p, g_h1p);
    cudaGetSymbolAddress((void**)&p_h1h, g_h1h);
    cudaGetSymbolAddress((void**)&p_h1l, g_h1l);
    cudaGetSymbolAddress((void**)&p_wb, g_wb);

    cudaFuncSetAttribute(k_wbgemm, cudaFuncAttributeMaxDynamicSharedMemorySize,
                         WB_SMEM_BYTES);
    cudaFuncSetAttribute(k_decode, cudaFuncAttributeMaxDynamicSharedMemorySize,
                         DEC_SMEM_BYTES);

    // 1) h1 split-K partials (fused h0 per chunk): 256 CTAs
    {
        dim3 grid(HID / 64, NB / 16, 4);
        k_h1split<<<grid, 128>>>(z, hw0, hb0, hw1, p_h1p);
    }

    // 2) h1 reduce + bias + leaky + fp16 split
    k_h1red<<<32, 1024>>>(p_h1p, hb1, p_h1h, p_h1l);

    // 3) wb = h1 @ hw2 + hb2 via fp16 mma (2-split), ldmatrix, 132 CTAs
    k_wbgemm<<<(OUTSZ + BNW - 1) / BNW, 256, WB_SMEM_BYTES>>>(
        p_h1h, p_h1l, hw2, hb2, p_wb);

    // 4) decoder on tensor cores (fp16 2-split, ldmatrix)
    k_decode<<<NB, 512, DEC_SMEM_BYTES>>>(logP, out);
}

// round 16
// speedup vs baseline: 1.3844x; 1.0384x over previous
#include <cuda_runtime.h>
#include <cuda_fp16.h>
#include <cstdint>

#define LATENT 16
#define HID 512
#define DD 64
#define NB 128
#define NG 128
#define OUTSZ 12610
#define OUTSZ_PAD 12612

// Scratch (device globals — no allocation allowed)
__device__ float g_h1p[4 * NB * HID];  // split-K partials of h1
__device__ __half g_h1h[NB * HID];     // fp16-hi split of h1, [m][k]
__device__ __half g_h1l[NB * HID];     // fp16-lo split of h1, [m][k]
__device__ float g_wb[NB * OUTSZ_PAD]; // PRE-PERMUTED into decoder layout

typedef unsigned long long u64;

__device__ __forceinline__ u64 pack2(float lo, float hi) {
    u64 r; asm("mov.b64 %0, {%1, %2};" : "=l"(r) : "f"(lo), "f"(hi)); return r;
}
__device__ __forceinline__ void fma2(u64& d, u64 a, u64 b) {
    asm("fma.rn.f32x2 %0, %1, %2, %0;" : "+l"(d) : "l"(a), "l"(b));
}

__device__ __forceinline__ float leaky(float x) { return x > 0.0f ? x : 0.01f * x; }

// fast sin: 2-step Cody-Waite range reduction + MUFU sin (args stay < ~40)
__device__ __forceinline__ float fsin(float x) {
    float k = rintf(x * 0.15915494309189535f);
    x = fmaf(k, -6.28125f, x);
    x = fmaf(k, -1.9353071795864769e-3f, x);
    return __sinf(x);
}

// pack two fp32 into one u32 of 2 fp16 (lo half = first arg)
__device__ __forceinline__ uint32_t packh2(float vlo, float vhi) {
    uint32_t d;
    asm("cvt.rn.f16x2.f32 %0, %1, %2;" : "=r"(d) : "f"(vhi), "f"(vlo));
    return d;
}

__device__ __forceinline__ uint32_t smem_u32(const void* p) {
    uint32_t a;
    asm("{ .reg .u64 t; cvta.to.shared.u64 t, %1; cvt.u32.u64 %0, t; }"
        : "=r"(a) : "l"(p));
    return a;
}

// ldmatrix: 4 / 2 8x8 b16 matrices per warp-collective instruction
__device__ __forceinline__ void ldsm4(uint32_t* r, uint32_t a) {
    asm volatile("ldmatrix.sync.aligned.m8n8.x4.shared.b16 {%0,%1,%2,%3}, [%4];"
                 : "=r"(r[0]), "=r"(r[1]), "=r"(r[2]), "=r"(r[3]) : "r"(a));
}
__device__ __forceinline__ void ldsm2(uint32_t* r, uint32_t a) {
    asm volatile("ldmatrix.sync.aligned.m8n8.x2.shared.b16 {%0,%1}, [%2];"
                 : "=r"(r[0]), "=r"(r[1]) : "r"(a));
}

// fp16 mma m16n8k16 (fragment mappings validated rounds 10-15)
__device__ __forceinline__ void mma_f16(float4& c, const uint32_t a[4],
                                        const uint32_t b[2]) {
    asm volatile(
        "mma.sync.aligned.m16n8k16.row.col.f32.f16.f16.f32 "
        "{%0,%1,%2,%3}, {%4,%5,%6,%7}, {%8,%9}, {%0,%1,%2,%3};"
        : "+f"(c.x), "+f"(c.y), "+f"(c.z), "+f"(c.w)
        : "r"(a[0]), "r"(a[1]), "r"(a[2]), "r"(a[3]), "r"(b[0]), "r"(b[1]));
}

// Decoder layout (floats): W1[0,4096) W2[4096,8192) W3[8192,12288) W0[12288,12352)
// b1[12352,12416) b2[12416,12480) b3[12480,12544) W4[12544,12608) b0[12608] b4[12609]
#define OFF_W0 12288
#define OFF_B  12352
#define OFF_W4 12544

__device__ __forceinline__ int perm_wb(int n) {
    if (n < 4161)  return (n < 64) ? 12288 + n : (n == 64 ? 12608 : n - 65);
    if (n < 8321)  return (n < 4225) ? 12352 + (n - 4161) : 4096 + (n - 4225);
    if (n < 12481) return (n < 8385) ? 12416 + (n - 8321) : 8192 + (n - 8385);
    if (n < 12545) return 12480 + (n - 12481);
    return (n < 12609) ? 12544 + (n - 12545) : 12609;
}

// ---------------------------------------------------------------------------
// h1 split-K GEMM with lean fused h0. Grid (8,8,4) = 256 CTAs x 128 thr.
// ---------------------------------------------------------------------------
#define H1_AD_STR 17

__global__ void __launch_bounds__(128)
k_h1split(const float* __restrict__ z, const float* __restrict__ hw0,
          const float* __restrict__ hb0, const float* __restrict__ hw1,
          float* __restrict__ partial) {
    __shared__ __align__(16) u64 Ad[128 * H1_AD_STR];
    __shared__ __align__(16) float Bs[2][16][64];
    __shared__ float zs[256];

    int tid = threadIdx.x;
    int tx = tid & 15, ty = tid >> 4;
    int n0 = blockIdx.x * 64;
    int m0 = blockIdx.y * 16;
    int kbase = blockIdx.z * 128;

    for (int e = tid; e < 256; e += 128) zs[e] = z[m0 * LATENT + e];
    __syncthreads();

    {
        int cg = kbase + tid;
        float hw0r[16];
#pragma unroll
        for (int k = 0; k < 16; k++) hw0r[k] = hw0[k * HID + cg];
        float bb = hb0[cg];
#pragma unroll
        for (int r = 0; r < 16; r++) {
            float acc = bb;
#pragma unroll
            for (int k = 0; k < 16; k++) acc = fmaf(zs[r * 16 + k], hw0r[k], acc);
            acc = leaky(acc);
            Ad[tid * H1_AD_STR + r] = pack2(acc, acc);
        }
    }

    u64 acc[2][2];
#pragma unroll
    for (int i = 0; i < 2; i++)
#pragma unroll
        for (int j = 0; j < 2; j++) acc[i][j] = pack2(0.0f, 0.0f);

    float pb[8];
    int pbn = tid & 63, pbk0 = tid >> 6;

    auto ldg_b = [&](int k0) {
#pragma unroll
        for (int r = 0; r < 8; r++)
            pb[r] = hw1[(size_t)(k0 + pbk0 + r * 2) * HID + n0 + pbn];
    };
    auto sts_b = [&](int s) {
#pragma unroll
        for (int r = 0; r < 8; r++) Bs[s][pbk0 + r * 2][pbn] = pb[r];
    };

    ldg_b(kbase);
    sts_b(0);
    __syncthreads();

    int p = 0;
    for (int t = 0; t < 8; t++) {
        if (t + 1 < 8) ldg_b(kbase + (t + 1) * 16);
#pragma unroll
        for (int k = 0; k < 16; k++) {
            int kk = t * 16 + k;
            u64 ra0 = Ad[kk * H1_AD_STR + ty * 2];
            u64 ra1 = Ad[kk * H1_AD_STR + ty * 2 + 1];
            u64 rb0 = *(const u64*)&Bs[p][k][tx * 2];
            u64 rb1 = *(const u64*)&Bs[p][k][tx * 2 + 32];
            fma2(acc[0][0], ra0, rb0); fma2(acc[0][1], ra0, rb1);
            fma2(acc[1][0], ra1, rb0); fma2(acc[1][1], ra1, rb1);
        }
        if (t + 1 < 8) {
            sts_b(p ^ 1);
            __syncthreads();
        }
        p ^= 1;
    }

    float* outp = partial + (size_t)blockIdx.z * (NB * HID);
#pragma unroll
    for (int i = 0; i < 2; i++) {
        int m = m0 + ty * 2 + i;
#pragma unroll
        for (int j = 0; j < 2; j++) {
            float lo, hi;
            asm("mov.b64 {%0, %1}, %2;" : "=f"(lo), "=f"(hi) : "l"(acc[i][j]));
            int n = n0 + tx * 2 + j * 32;
            outp[(size_t)m * HID + n] = lo;
            outp[(size_t)m * HID + n + 1] = hi;
        }
    }
}

// ---------------------------------------------------------------------------
// h1 reduce: sum 4 partials + bias + leaky + fp16 hi/lo split.
// ---------------------------------------------------------------------------
__global__ void __launch_bounds__(1024)
k_h1red(const float* __restrict__ partial, const float* __restrict__ bias,
        __half* __restrict__ Ch, __half* __restrict__ Cl) {
    int p = blockIdx.x * 1024 + threadIdx.x;
    int m = p >> 8;
    int n = (p & 255) * 2;
    const float* base = partial + (size_t)m * HID + n;
    float2 s0 = *(const float2*)(base);
    float2 s1 = *(const float2*)(base + NB * HID);
    float2 s2 = *(const float2*)(base + 2 * NB * HID);
    float2 s3 = *(const float2*)(base + 3 * NB * HID);
    float v0 = leaky(s0.x + s1.x + s2.x + s3.x + bias[n]);
    float v1 = leaky(s0.y + s1.y + s2.y + s3.y + bias[n + 1]);
    float h0f = __half2float(__float2half_rn(v0));
    float h1f = __half2float(__float2half_rn(v1));
    *(uint32_t*)&Ch[(size_t)m * HID + n] = packh2(h0f, h1f);
    *(uint32_t*)&Cl[(size_t)m * HID + n] = packh2(v0 - h0f, v1 - h1f);
}

// ---------------------------------------------------------------------------
// wb GEMM via fp16 mma (2-split), 132 CTAs x 256 threads, warp m64 x n24,
// double-buffered + ldmatrix; K-tile 64 (8 iterations, 8 syncs).
// ---------------------------------------------------------------------------
#define KT 64
#define BNW 96
#define ASTR 72
#define BSTR 72
#define STG_H (2 * 128 * ASTR + 2 * BNW * BSTR)   // halves per stage
#define WB_SMEM_BYTES (2 * STG_H * 2)

__global__ void __launch_bounds__(256)
k_wbgemm(const __half* __restrict__ Ah_g, const __half* __restrict__ Al_g,
         const float* __restrict__ Bg, const float* __restrict__ bias,
         float* __restrict__ Cout) {
    extern __shared__ __align__(16) __half smh[];
    uint32_t sb = smem_u32(smh);

    int tid = threadIdx.x;
    int lane = tid & 31;
    int wid = tid >> 5;
    int g4 = lane >> 2;
    int t4 = lane & 3;
    int wm = wid & 1;        // m-half (64 rows)
    int wn = wid >> 1;       // n-quarter (24 cols)
    int n0 = blockIdx.x * BNW;

    int bn = tid % BNW, bkh = tid / BNW;     // B staging: threads < 192
    bool bact = tid < 192;
    bool bok = bact && (n0 + bn) < OUTSZ;
    int brot = (bn >> 3) & 15;

    // ldmatrix row offsets (halves)
    int rA = (wm * 64 + (lane & 15)) * ASTR + (lane >> 4) * 8;
    int rB01 = (wn * 24 + (lane & 7) + ((lane >> 4) << 3)) * BSTR
             + ((lane >> 3) & 1) * 8;
    int rB2 = (wn * 24 + 16 + (lane & 7)) * BSTR + ((lane >> 3) & 1) * 8;

    float4 acc[4][3];
#pragma unroll
    for (int i = 0; i < 4; i++)
#pragma unroll
        for (int j = 0; j < 3; j++) acc[i][j] = make_float4(0.f, 0.f, 0.f, 0.f);

    u64 pah[8], pal[8];
    float pb[32];

    auto ldg_tile = [&](int kt) {
#pragma unroll
        for (int i = 0; i < 8; i++) {
            int idx = tid + i * 256;          // 2048 u64 slots (128 rows x 16)
            int m = idx >> 4, j = idx & 15;
            pah[i] = *(const u64*)&Ah_g[(size_t)m * HID + kt + j * 4];
            pal[i] = *(const u64*)&Al_g[(size_t)m * HID + kt + j * 4];
        }
        if (bact) {
            const float* bp = Bg + (size_t)(kt + bkh * 32) * OUTSZ + n0 + bn;
#pragma unroll
            for (int j = 0; j < 32; j++)
                pb[j] = bok ? bp[(size_t)j * OUTSZ] : 0.0f;
        }
    };
    auto sts_tile = [&](int s) {
        __half* As_h = smh + s * STG_H;
        __half* As_l = As_h + 128 * ASTR;
        __half* Bs_h = As_l + 128 * ASTR;
        __half* Bs_l = Bs_h + BNW * BSTR;
#pragma unroll
        for (int i = 0; i < 8; i++) {
            int idx = tid + i * 256;
            int m = idx >> 4, j = idx & 15;
            *(u64*)&As_h[m * ASTR + j * 4] = pah[i];
            *(u64*)&As_l[m * ASTR + j * 4] = pal[i];
        }
        if (bact) {
#pragma unroll
            for (int s2 = 0; s2 < 16; s2++) {
                int jr = (s2 + brot) & 15;           // rotated store order
                float v0 = pb[2 * jr], v1 = pb[2 * jr + 1];
                float h0 = __half2float(__float2half_rn(v0));
                float h1 = __half2float(__float2half_rn(v1));
                *(uint32_t*)&Bs_h[bn * BSTR + bkh * 32 + 2 * jr] = packh2(h0, h1);
                *(uint32_t*)&Bs_l[bn * BSTR + bkh * 32 + 2 * jr] =
                    packh2(v0 - h0, v1 - h1);
            }
        }
    };

    ldg_tile(0);
    sts_tile(0);
    __syncthreads();

    int p = 0;
    for (int t = 0; t < HID / KT; t++) {
        if (t + 1 < HID / KT) ldg_tile((t + 1) * KT);

        uint32_t bAh = sb + 2 * (p * STG_H);
        uint32_t bAl = bAh + 2 * 128 * ASTR;
        uint32_t bBh = bAl + 2 * 128 * ASTR;
        uint32_t bBl = bBh + 2 * BNW * BSTR;

#pragma unroll
        for (int ks = 0; ks < KT; ks += 16) {
            uint32_t ah[4][4], al[4][4];
#pragma unroll
            for (int mf = 0; mf < 4; mf++) {
                ldsm4(ah[mf], bAh + 2 * (rA + mf * 16 * ASTR + ks));
                ldsm4(al[mf], bAl + 2 * (rA + mf * 16 * ASTR + ks));
            }
            uint32_t b01h[4], b01l[4], b2h[2], b2l[2];
            ldsm4(b01h, bBh + 2 * (rB01 + ks));
            ldsm4(b01l, bBl + 2 * (rB01 + ks));
            ldsm2(b2h, bBh + 2 * (rB2 + ks));
            ldsm2(b2l, bBl + 2 * (rB2 + ks));
#pragma unroll
            for (int mf = 0; mf < 4; mf++) {
                mma_f16(acc[mf][0], ah[mf], b01h);
                mma_f16(acc[mf][0], ah[mf], b01l);
                mma_f16(acc[mf][0], al[mf], b01h);
                mma_f16(acc[mf][1], ah[mf], b01h + 2);
                mma_f16(acc[mf][1], ah[mf], b01l + 2);
                mma_f16(acc[mf][1], al[mf], b01h + 2);
                mma_f16(acc[mf][2], ah[mf], b2h);
                mma_f16(acc[mf][2], ah[mf], b2l);
                mma_f16(acc[mf][2], al[mf], b2h);
            }
        }
        if (t + 1 < HID / KT) {
            sts_tile(p ^ 1);
            __syncthreads();
        }
        p ^= 1;
    }

    // epilogue: bias + permuted scatter
#pragma unroll
    for (int mf = 0; mf < 4; mf++) {
        int m = wm * 64 + mf * 16 + g4;
#pragma unroll
        for (int nf = 0; nf < 3; nf++) {
            int n = n0 + wn * 24 + nf * 8 + t4 * 2;
            if (n < OUTSZ) {
                Cout[(size_t)m * OUTSZ_PAD + perm_wb(n)] = acc[mf][nf].x + bias[n];
                Cout[(size_t)(m + 8) * OUTSZ_PAD + perm_wb(n)] = acc[mf][nf].z + bias[n];
            }
            if (n + 1 < OUTSZ) {
                Cout[(size_t)m * OUTSZ_PAD + perm_wb(n + 1)] = acc[mf][nf].y + bias[n + 1];
                Cout[(size_t)(m + 8) * OUTSZ_PAD + perm_wb(n + 1)] = acc[mf][nf].w + bias[n + 1];
            }
        }
    }
}

// ---------------------------------------------------------------------------
// Decoder via fp16 mma (2-split), 1024 threads (32 warps: wm 0..7 m16,
// wn 0..3 n16), ldmatrix + next-layer W prefetch.
// ---------------------------------------------------------------------------
#define XSH 72
#define WSH 72
#define XBUFH (NG * XSH)          // 9216 halves
#define WBUFH (DD * WSH)          // 4608 halves
#define DEC_SMEM_BYTES ((4 * XBUFH + 2 * WBUFH) * 2 + 1024 * 4)

__global__ void __launch_bounds__(1024)
k_decode(const float* __restrict__ logP, float* __restrict__ out) {
    extern __shared__ __align__(16) __half smh[];
    __half* XAh = smh;
    __half* XAl = smh + XBUFH;
    __half* XBh = smh + 2 * XBUFH;
    __half* XBl = smh + 3 * XBUFH;
    __half* Wth = smh + 4 * XBUFH;
    __half* Wtl = smh + 4 * XBUFH + WBUFH;
    float* part = (float*)(smh + 4 * XBUFH + 2 * WBUFH);
    uint32_t sb = smem_u32(smh);
    uint32_t bXA_h = sb, bXA_l = sb + 2 * XBUFH;
    uint32_t bXB_h = sb + 4 * XBUFH, bXB_l = sb + 6 * XBUFH;
    uint32_t bW_h = sb + 8 * XBUFH, bW_l = bW_h + 2 * WBUFH;

    int b = blockIdx.x;
    int tid = threadIdx.x;
    int lane = tid & 31;
    int wid = tid >> 5;
    int g4 = lane >> 2;
    int t4 = lane & 3;
    int wm = wid & 7;          // m-sixteenth (16 rows)
    int wn = wid >> 3;         // n-sixteenth (16 cols), 0..3
    const float* brow = g_wb + (size_t)b * OUTSZ_PAD;

    // ldmatrix row offsets (halves)
    int rX = (wm * 16 + (lane & 15)) * XSH + (lane >> 4) * 8;
    int rW = (wn * 16 + (lane & 7) + ((lane >> 4) << 3)) * WSH
           + ((lane >> 3) & 1) * 8;

    // W staging map: consecutive lanes -> consecutive i (conflict-light)
    int wsi = tid & 63;                 // W row i
    int wsj0 = (tid >> 6) * 4;          // 4 consecutive j per thread
    float wv[4];
    {
        float4 wa = *(const float4*)&brow[wsi * DD + wsj0];
        wv[0] = wa.x; wv[1] = wa.y; wv[2] = wa.z; wv[3] = wa.w;
    }

    // ---- first layer: X0 = sin(30*(xin*W0 + b0)), fp16 hi/lo, rotated ----
    {
        int g = tid & (NG - 1);
        int q = tid >> 7;                    // 0..7, 8 j each
        int rot = (g >> 3) & 3;
        float xin = logP[b * NG + g];
        float b0v = brow[12608];
#pragma unroll
        for (int s = 0; s < 4; s++) {
            int j = q * 8 + 2 * ((s + rot) & 3);
            float v0 = fsin(30.0f * fmaf(xin, brow[OFF_W0 + j], b0v));
            float v1 = fsin(30.0f * fmaf(xin, brow[OFF_W0 + j + 1], b0v));
            float h0 = __half2float(__float2half_rn(v0));
            float h1 = __half2float(__float2half_rn(v1));
            *(uint32_t*)&XAh[g * XSH + j] = packh2(h0, h1);
            *(uint32_t*)&XAl[g * XSH + j] = packh2(v0 - h0, v1 - h1);
        }
    }
    __syncthreads();

#pragma unroll 1
    for (int it = 0; it < 3; it++) {
        // stage W transposed, fp16 hi/lo
#pragma unroll
        for (int jj = 0; jj < 4; jj++) {
            int j = wsj0 + jj;
            float hf = __half2float(__float2half_rn(wv[jj]));
            Wth[j * WSH + wsi] = __float2half_rn(hf);
            Wtl[j * WSH + wsi] = __float2half_rn(wv[jj] - hf);
        }
        float biasE[2], biasO[2];
#pragma unroll
        for (int nf = 0; nf < 2; nf++) {
            int col = wn * 16 + nf * 8 + 2 * t4;
            biasE[nf] = brow[OFF_B + it * DD + col];
            biasO[nf] = brow[OFF_B + it * DD + col + 1];
        }
        __syncthreads();

        // prefetch next layer's W (overlaps MMA below)
        float wvn[4];
        if (it < 2) {
            float4 wa = *(const float4*)&brow[(it + 1) * DD * DD + wsi * DD + wsj0];
            wvn[0] = wa.x; wvn[1] = wa.y; wvn[2] = wa.z; wvn[3] = wa.w;
        }

        uint32_t bXh = (it & 1) ? bXB_h : bXA_h;
        uint32_t bXl = (it & 1) ? bXB_l : bXA_l;
        __half* Xoh = (it & 1) ? XAh : XBh;
        __half* Xol = (it & 1) ? XAl : XBl;

        float4 acc[2];
#pragma unroll
        for (int nf = 0; nf < 2; nf++)
            acc[nf] = make_float4(biasE[nf], biasO[nf], biasE[nf], biasO[nf]);

        int m = wm * 16 + g4;
#pragma unroll
        for (int k16 = 0; k16 < DD; k16 += 16) {
            uint32_t ah[4], al[4], bh[4], bl[4];
            ldsm4(ah, bXh + 2 * (rX + k16));
            ldsm4(al, bXl + 2 * (rX + k16));
            ldsm4(bh, bW_h + 2 * (rW + k16));
            ldsm4(bl, bW_l + 2 * (rW + k16));
            mma_f16(acc[0], ah, bh);
            mma_f16(acc[0], ah, bl);
            mma_f16(acc[0], al, bh);
            mma_f16(acc[1], ah, bh + 2);
            mma_f16(acc[1], ah, bl + 2);
            mma_f16(acc[1], al, bh + 2);
        }

        // sin + split + store (c0,c1 -> row m; c2,c3 -> row m+8)
#pragma unroll
        for (int nf = 0; nf < 2; nf++) {
            int col = wn * 16 + nf * 8 + 2 * t4;
            float4 a = acc[nf];
            float v0 = fsin(a.x), v1 = fsin(a.y);
            float v2 = fsin(a.z), v3 = fsin(a.w);
            float h0 = __half2float(__float2half_rn(v0));
            float h1 = __half2float(__float2half_rn(v1));
            float h2 = __half2float(__float2half_rn(v2));
            float h3 = __half2float(__float2half_rn(v3));
            *(uint32_t*)&Xoh[m * XSH + col] = packh2(h0, h1);
            *(uint32_t*)&Xol[m * XSH + col] = packh2(v0 - h0, v1 - h1);
            *(uint32_t*)&Xoh[(m + 8) * XSH + col] = packh2(h2, h3);
            *(uint32_t*)&Xol[(m + 8) * XSH + col] = packh2(v2 - h2, v3 - h3);
        }
        __syncthreads();
#pragma unroll
        for (int q = 0; q < 4; q++) wv[q] = wvn[q];
    }

    // ---- final layer: out[g] = (X3 . W4) + b4 (X3 in XB after it=2) ----
    {
        int g = tid & (NG - 1);
        int q = tid >> 7;                    // 0..7, 8 i each
        float s = 0.0f;
#pragma unroll
        for (int ii = 0; ii < 8; ii++) {
            int i = q * 8 + ii;
            float xv = __half2float(XBh[g * XSH + i]) + __half2float(XBl[g * XSH + i]);
            s = fmaf(xv, brow[OFF_W4 + i], s);
        }
        part[q * NG + g] = s;
    }
    __syncthreads();
    if (tid < NG) {
        float acc = brow[12609];
#pragma unroll
        for (int q = 0; q < 8; q++) acc += part[q * NG + tid];
        out[b * NG + tid] = fmaf(acc, 500.0f, 1500.0f);
    }
}

// ---------------------------------------------------------------------------
extern "C" void kernel_launch(void* const* d_in, const int* in_sizes, int n_in,
                              void* d_out, int out_size) {
    (void)in_sizes; (void)n_in; (void)out_size;
    const float* z    = (const float*)d_in[0];
    const float* logP = (const float*)d_in[1];
    const float* hw0  = (const float*)d_in[2];
    const float* hb0  = (const float*)d_in[3];
    const float* hw1  = (const float*)d_in[4];
    const float* hb1  = (const float*)d_in[5];
    const float* hw2  = (const float*)d_in[6];
    const float* hb2  = (const float*)d_in[7];
    float* out = (float*)d_out;

    float *p_wb, *p_h1p;
    __half *p_h1h, *p_h1l;
    cudaGetSymbolAddress((void**)&p_h1p, g_h1p);
    cudaGetSymbolAddress((void**)&p_h1h, g_h1h);
    cudaGetSymbolAddress((void**)&p_h1l, g_h1l);
    cudaGetSymbolAddress((void**)&p_wb, g_wb);

    cudaFuncSetAttribute(k_wbgemm, cudaFuncAttributeMaxDynamicSharedMemorySize,
                         WB_SMEM_BYTES);
    cudaFuncSetAttribute(k_decode, cudaFuncAttributeMaxDynamicSharedMemorySize,
                         DEC_SMEM_BYTES);

    // 1) h1 split-K partials (fused h0 per chunk): 256 CTAs
    {
        dim3 grid(HID / 64, NB / 16, 4);
        k_h1split<<<grid, 128>>>(z, hw0, hb0, hw1, p_h1p);
    }

    // 2) h1 reduce + bias + leaky + fp16 split
    k_h1red<<<32, 1024>>>(p_h1p, hb1, p_h1h, p_h1l);

    // 3) wb = h1 @ hw2 + hb2 via fp16 mma (2-split), ldmatrix, KT=64
    k_wbgemm<<<(OUTSZ + BNW - 1) / BNW, 256, WB_SMEM_BYTES>>>(
        p_h1h, p_h1l, hw2, hb2, p_wb);

    // 4) decoder on tensor cores (fp16 2-split, ldmatrix, 1024 thr)
    k_decode<<<NB, 1024, DEC_SMEM_BYTES>>>(logP, out);
}